// round 3
// baseline (speedup 1.0000x reference)
#include <cuda_runtime.h>
#include <cuda_bf16.h>
#include <math.h>

// ---------------- problem constants ----------------
#define BB   32
#define TT   128
#define BT   4096          // B*T
#define DIN  4096          // D_RGB + D_FLOW
#define EE   1024
#define HH   2048
#define H3   6144
#define CC   22
#define KQ   1024
#define CDIM 128
#define MOM  0.999f

// output offsets (float32 concat: q_cls, k_cls, new_queues, new_ptrs)
#define OUT_Q      0
#define OUT_K      4096
#define OUT_QUEUE  8192
#define OUT_PTR    (8192 + CC*CDIM*KQ)

// ---------------- device scratch (zero-init .bss; allowed) ----------------
__device__ float g_w1k [DIN*EE];        // momentum-updated key params
__device__ float g_wihk[H3*EE];
__device__ float g_whhk[H3*HH];
__device__ float g_b1k [EE];
__device__ float g_gk  [EE];
__device__ float g_bek [EE];
__device__ float g_bihk[H3];
__device__ float g_bhhk[H3];

__device__ float g_xq  [BT*DIN];        // masked concat (query)
__device__ float g_xk  [BT*DIN];        // unmasked concat (key)
__device__ float g_x1q [BT*EE];
__device__ float g_x1k [BT*EE];
__device__ float g_xiq [BT*H3];
__device__ float g_xik [BT*H3];

__device__ float g_hq  [2][BB*HH];      // ping-pong hidden state
__device__ float g_hk  [2][BB*HH];

__device__ int   g_slot[BB*CC];

// ---------------- momentum update ----------------
__global__ void mom_w1(const float* __restrict__ kp, const float* __restrict__ qp) {
    for (int i = blockIdx.x*blockDim.x + threadIdx.x; i < DIN*EE; i += gridDim.x*blockDim.x)
        g_w1k[i] = MOM*kp[i] + (1.0f - MOM)*qp[i];
}
__global__ void mom_wih(const float* __restrict__ kp, const float* __restrict__ qp) {
    for (int i = blockIdx.x*blockDim.x + threadIdx.x; i < H3*EE; i += gridDim.x*blockDim.x)
        g_wihk[i] = MOM*kp[i] + (1.0f - MOM)*qp[i];
}
__global__ void mom_whh(const float* __restrict__ kp, const float* __restrict__ qp) {
    for (int i = blockIdx.x*blockDim.x + threadIdx.x; i < H3*HH; i += gridDim.x*blockDim.x)
        g_whhk[i] = MOM*kp[i] + (1.0f - MOM)*qp[i];
}
__global__ void mom_vec(const float* b1k, const float* b1q,
                        const float* gk,  const float* gq,
                        const float* bek, const float* beq,
                        const float* bihk,const float* bihq,
                        const float* bhhk,const float* bhhq) {
    int i = blockIdx.x*blockDim.x + threadIdx.x;
    if (i < EE) {
        g_b1k[i] = MOM*b1k[i] + (1.0f-MOM)*b1q[i];
        g_gk [i] = MOM*gk [i] + (1.0f-MOM)*gq [i];
        g_bek[i] = MOM*bek[i] + (1.0f-MOM)*beq[i];
    }
    if (i < H3) {
        g_bihk[i] = MOM*bihk[i] + (1.0f-MOM)*bihq[i];
        g_bhhk[i] = MOM*bhhk[i] + (1.0f-MOM)*bhhq[i];
    }
}

// ---------------- build masked / unmasked concat inputs ----------------
__global__ void build_inputs(const float* __restrict__ rgb, const float* __restrict__ flow,
                             const float* __restrict__ rmask) {
    for (int i = blockIdx.x*blockDim.x + threadIdx.x; i < BT*DIN; i += gridDim.x*blockDim.x) {
        int bt = i >> 12;          // /4096
        int c  = i & 4095;
        int t  = bt & (TT-1);
        float m = (t == TT-1 || rmask[bt] > 0.25f) ? 1.0f : 0.0f;
        float v = (c < 2048) ? rgb[(size_t)bt*2048 + c] : flow[(size_t)bt*2048 + (c-2048)];
        g_xq[i] = v * m;
        g_xk[i] = v;
    }
}

// ---------------- tiled SGEMM: C[M,N] = A[M,K] * op(B) + bias ----------------
// TB=false: B is [K,N] row-major.  TB=true: B is [N,K] row-major (i.e. C = A*B^T).
template<bool TB>
__global__ __launch_bounds__(256)
void sgemm(const float* __restrict__ A, const float* __restrict__ Bm,
           const float* __restrict__ bias, float* __restrict__ C,
           int M, int N, int K) {
    __shared__ float As[16][65];
    __shared__ float Bs[16][65];
    const int tid = threadIdx.x;
    const int tx = tid & 15, ty = tid >> 4;
    const int m0 = blockIdx.y * 64, n0 = blockIdx.x * 64;
    const int la_m = tid >> 2, la_k = (tid & 3) * 4;

    float acc[4][4];
#pragma unroll
    for (int i = 0; i < 4; i++)
#pragma unroll
        for (int j = 0; j < 4; j++) acc[i][j] = 0.0f;

    for (int k0 = 0; k0 < K; k0 += 16) {
        float4 av = *(const float4*)(A + (size_t)(m0 + la_m)*K + k0 + la_k);
        As[la_k  ][la_m] = av.x; As[la_k+1][la_m] = av.y;
        As[la_k+2][la_m] = av.z; As[la_k+3][la_m] = av.w;
        if (!TB) {
            int bk = tid >> 4, bn = (tid & 15) * 4;
            float4 bv = *(const float4*)(Bm + (size_t)(k0 + bk)*N + n0 + bn);
            Bs[bk][bn] = bv.x; Bs[bk][bn+1] = bv.y; Bs[bk][bn+2] = bv.z; Bs[bk][bn+3] = bv.w;
        } else {
            float4 bv = *(const float4*)(Bm + (size_t)(n0 + la_m)*K + k0 + la_k);
            Bs[la_k  ][la_m] = bv.x; Bs[la_k+1][la_m] = bv.y;
            Bs[la_k+2][la_m] = bv.z; Bs[la_k+3][la_m] = bv.w;
        }
        __syncthreads();
#pragma unroll
        for (int k = 0; k < 16; k++) {
            float a0 = As[k][ty*4+0], a1 = As[k][ty*4+1], a2 = As[k][ty*4+2], a3 = As[k][ty*4+3];
            float b0 = Bs[k][tx*4+0], b1 = Bs[k][tx*4+1], b2 = Bs[k][tx*4+2], b3 = Bs[k][tx*4+3];
            acc[0][0] += a0*b0; acc[0][1] += a0*b1; acc[0][2] += a0*b2; acc[0][3] += a0*b3;
            acc[1][0] += a1*b0; acc[1][1] += a1*b1; acc[1][2] += a1*b2; acc[1][3] += a1*b3;
            acc[2][0] += a2*b0; acc[2][1] += a2*b1; acc[2][2] += a2*b2; acc[2][3] += a2*b3;
            acc[3][0] += a3*b0; acc[3][1] += a3*b1; acc[3][2] += a3*b2; acc[3][3] += a3*b3;
        }
        __syncthreads();
    }
#pragma unroll
    for (int i = 0; i < 4; i++)
#pragma unroll
        for (int j = 0; j < 4; j++) {
            int n = n0 + tx*4 + j;
            C[(size_t)(m0 + ty*4 + i)*N + n] = acc[i][j] + bias[n];
        }
}

// ---------------- LayerNorm + ReLU (in place), rows of EE=1024 ----------------
__global__ __launch_bounds__(256)
void ln_relu(float* __restrict__ x, const float* __restrict__ g, const float* __restrict__ be) {
    int row = blockIdx.x;
    int tid = threadIdx.x;
    float4* xr = (float4*)(x + (size_t)row * EE);
    float4 v = xr[tid];
    float s  = v.x + v.y + v.z + v.w;
    float ss = v.x*v.x + v.y*v.y + v.z*v.z + v.w*v.w;
#pragma unroll
    for (int o = 16; o; o >>= 1) {
        s  += __shfl_xor_sync(0xffffffffu, s,  o);
        ss += __shfl_xor_sync(0xffffffffu, ss, o);
    }
    __shared__ float sh_s[8], sh_ss[8];
    if ((tid & 31) == 0) { sh_s[tid >> 5] = s; sh_ss[tid >> 5] = ss; }
    __syncthreads();
    float S = 0.0f, SS = 0.0f;
#pragma unroll
    for (int w = 0; w < 8; w++) { S += sh_s[w]; SS += sh_ss[w]; }
    float mu   = S * (1.0f / EE);
    float var  = SS * (1.0f / EE) - mu * mu;
    float rstd = rsqrtf(var + 1e-5f);
    int c = tid * 4;
    float4 gg = *(const float4*)(g  + c);
    float4 bb = *(const float4*)(be + c);
    float4 y;
    y.x = fmaxf((v.x - mu) * rstd * gg.x + bb.x, 0.0f);
    y.y = fmaxf((v.y - mu) * rstd * gg.y + bb.y, 0.0f);
    y.z = fmaxf((v.z - mu) * rstd * gg.z + bb.z, 0.0f);
    y.w = fmaxf((v.w - mu) * rstd * gg.w + bb.w, 0.0f);
    xr[tid] = y;
}

// ---------------- init hidden state ----------------
__global__ void h_init() {
    int i = blockIdx.x*blockDim.x + threadIdx.x;
    if (i < BB*HH) { g_hq[0][i] = 0.0f; g_hk[0][i] = 0.0f; }
}

// ---------------- one GRU step (both encoders), fused hh-GEMM + gates ----------------
// grid: (HH/32, 2); block: 256 threads.  jj = tid&31 (column in j-tile), ty = tid>>5,
// each thread: 4 batch rows {ty, ty+8, ty+16, ty+24} x 3 gates.
__global__ __launch_bounds__(256)
void gru_step(int t, int par,
              const float* __restrict__ whh_q, const float* __restrict__ bhh_q) {
    const int enc = blockIdx.y;
    const int j0  = blockIdx.x * 32;
    const int tid = threadIdx.x;
    const int jj  = tid & 31;
    const int ty  = tid >> 5;

    const float* whh  = enc ? g_whhk : whh_q;
    const float* bhh  = enc ? g_bhhk : bhh_q;
    const float* xi   = enc ? g_xik  : g_xiq;
    const float* hold = (enc ? g_hk[par]     : g_hq[par]);
    float*       hnew = (enc ? g_hk[par ^ 1] : g_hq[par ^ 1]);

    __shared__ float Hs[32][33];   // [k][b]
    __shared__ float Ws[96][33];   // [gate*32+jj][k]

    float acc[4][3];
#pragma unroll
    for (int i = 0; i < 4; i++)
#pragma unroll
        for (int gI = 0; gI < 3; gI++) acc[i][gI] = 0.0f;

    for (int k0 = 0; k0 < HH; k0 += 32) {
#pragma unroll
        for (int l = 0; l < 4; l++) {
            int idx = tid + l * 256;      // 0..1023
            int k = idx & 31, b = idx >> 5;
            Hs[k][b] = hold[(size_t)b*HH + k0 + k];
        }
#pragma unroll
        for (int l = 0; l < 12; l++) {
            int idx = tid + l * 256;      // 0..3071
            int k = idx & 31, r = idx >> 5;       // r in [0,96)
            int n = (r >> 5) * HH + j0 + (r & 31);
            Ws[r][k] = whh[(size_t)n*HH + k0 + k];
        }
        __syncthreads();
#pragma unroll
        for (int k = 0; k < 32; k++) {
            float h0 = Hs[k][ty], h1 = Hs[k][ty+8], h2 = Hs[k][ty+16], h3 = Hs[k][ty+24];
            float w0 = Ws[jj][k], w1 = Ws[32+jj][k], w2 = Ws[64+jj][k];
            acc[0][0] += h0*w0; acc[0][1] += h0*w1; acc[0][2] += h0*w2;
            acc[1][0] += h1*w0; acc[1][1] += h1*w1; acc[1][2] += h1*w2;
            acc[2][0] += h2*w0; acc[2][1] += h2*w1; acc[2][2] += h2*w2;
            acc[3][0] += h3*w0; acc[3][1] += h3*w1; acc[3][2] += h3*w2;
        }
        __syncthreads();
    }

    const int j = j0 + jj;
    const float bh_r = bhh[j], bh_z = bhh[HH + j], bh_n = bhh[2*HH + j];
#pragma unroll
    for (int i = 0; i < 4; i++) {
        int b = ty + i * 8;
        const float* xir = xi + (size_t)(b*TT + t) * H3;
        float hr = acc[i][0] + bh_r;
        float hz = acc[i][1] + bh_z;
        float hn = acc[i][2] + bh_n;
        float r  = 1.0f / (1.0f + expf(-(xir[j]        + hr)));
        float z  = 1.0f / (1.0f + expf(-(xir[HH + j]   + hz)));
        float nn = tanhf(xir[2*HH + j] + r * hn);
        float hp = hold[(size_t)b*HH + j];
        hnew[(size_t)b*HH + j] = (1.0f - z) * nn + z * hp;
    }
}

// ---------------- projection + l2norm: out[enc*4096 + b*128 + d] ----------------
__global__ __launch_bounds__(128)
void proj_l2(const float* __restrict__ wq, const float* __restrict__ bq, float* __restrict__ out) {
    const int enc = blockIdx.y, b = blockIdx.x, d = threadIdx.x;
    const float* h = (enc ? g_hk[0] : g_hq[0]) + (size_t)b * HH;
    float acc = bq[d];
#pragma unroll 4
    for (int k = 0; k < HH; k++)
        acc = fmaf(fmaxf(h[k], 0.0f), wq[(size_t)k*CDIM + d], acc);
    __shared__ float sh[128];
    sh[d] = acc * acc;
    __syncthreads();
#pragma unroll
    for (int o = 64; o; o >>= 1) { if (d < o) sh[d] += sh[d + o]; __syncthreads(); }
    out[enc*4096 + b*CDIM + d] = acc * rsqrtf(sh[0]);
}

// ---------------- queue: copy, slot metadata, scatter, ptrs ----------------
__global__ void queue_copy(const float* __restrict__ q, float* __restrict__ out) {
    const float4* src = (const float4*)q;
    float4* dst = (float4*)(out + OUT_QUEUE);
    for (int i = blockIdx.x*blockDim.x + threadIdx.x; i < (CC*CDIM*KQ)/4; i += gridDim.x*blockDim.x)
        dst[i] = src[i];
}
__global__ void queue_meta(const float* __restrict__ targets, const int* __restrict__ ptrs,
                           float* __restrict__ out) {
    int c = threadIdx.x;
    if (c < CC) {
        int cnt = 0;
        int p = ptrs[c];
        for (int b = 0; b < BB; b++) {
            if (targets[b*CC + c] > 0.5f) { g_slot[b*CC + c] = (p + cnt) % KQ; cnt++; }
            else                            g_slot[b*CC + c] = -1;
        }
        out[OUT_PTR + c] = (float)((p + cnt) % KQ);
    }
}
__global__ __launch_bounds__(128)
void queue_scatter(float* __restrict__ out) {
    int bc = blockIdx.x;            // b*CC + c
    int b = bc / CC, c = bc % CC;
    int s = g_slot[b*CC + c];
    if (s < 0) return;
    int d = threadIdx.x;
    float v = out[OUT_K + b*CDIM + d];                 // k_cls
    out[OUT_QUEUE + (size_t)c*CDIM*KQ + (size_t)d*KQ + s] = v;
}

// ---------------- host launch ----------------
extern "C" void kernel_launch(void* const* d_in, const int* in_sizes, int n_in,
                              void* d_out, int out_size) {
    const float* rgb    = (const float*)d_in[0];
    const float* flow   = (const float*)d_in[1];
    const float* rmask  = (const float*)d_in[2];
    const float* targets= (const float*)d_in[3];
    const float* w1_q   = (const float*)d_in[4];
    const float* b1_q   = (const float*)d_in[5];
    const float* gv_q   = (const float*)d_in[6];
    const float* be_q   = (const float*)d_in[7];
    const float* wih_q  = (const float*)d_in[8];
    const float* whh_q  = (const float*)d_in[9];
    const float* bih_q  = (const float*)d_in[10];
    const float* bhh_q  = (const float*)d_in[11];
    const float* w1_k   = (const float*)d_in[12];
    const float* b1_k   = (const float*)d_in[13];
    const float* gv_k   = (const float*)d_in[14];
    const float* be_k   = (const float*)d_in[15];
    const float* wih_k  = (const float*)d_in[16];
    const float* whh_k  = (const float*)d_in[17];
    const float* bih_k  = (const float*)d_in[18];
    const float* bhh_k  = (const float*)d_in[19];
    const float* wq     = (const float*)d_in[20];
    const float* bq     = (const float*)d_in[21];
    // disambiguate ptrs / queues by element count
    int ptrs_idx = (in_sizes[22] == CC) ? 22 : 23;
    int queues_idx = 45 - ptrs_idx;
    const int*   ptrs   = (const int*)d_in[ptrs_idx];
    const float* queues = (const float*)d_in[queues_idx];
    float* out = (float*)d_out;

    // 1. momentum update of key params
    mom_w1 <<<4096, 256>>>(w1_k,  w1_q);
    mom_wih<<<4096, 256>>>(wih_k, wih_q);
    mom_whh<<<8192, 256>>>(whh_k, whh_q);
    mom_vec<<<(H3 + 255)/256, 256>>>(b1_k, b1_q, gv_k, gv_q, be_k, be_q,
                                     bih_k, bih_q, bhh_k, bhh_q);

    // 2. build inputs
    build_inputs<<<16384, 256>>>(rgb, flow, rmask);

    // 3. layer1 GEMMs + LN/ReLU + GRU input GEMMs
    {
        float *p_xq, *p_xk, *p_x1q, *p_x1k, *p_xiq, *p_xik;
        float *p_w1k, *p_wihk, *p_b1k, *p_gk, *p_bek, *p_bihk;
        cudaGetSymbolAddress((void**)&p_xq,  g_xq);
        cudaGetSymbolAddress((void**)&p_xk,  g_xk);
        cudaGetSymbolAddress((void**)&p_x1q, g_x1q);
        cudaGetSymbolAddress((void**)&p_x1k, g_x1k);
        cudaGetSymbolAddress((void**)&p_xiq, g_xiq);
        cudaGetSymbolAddress((void**)&p_xik, g_xik);
        cudaGetSymbolAddress((void**)&p_w1k, g_w1k);
        cudaGetSymbolAddress((void**)&p_wihk,g_wihk);
        cudaGetSymbolAddress((void**)&p_b1k, g_b1k);
        cudaGetSymbolAddress((void**)&p_gk,  g_gk);
        cudaGetSymbolAddress((void**)&p_bek, g_bek);
        cudaGetSymbolAddress((void**)&p_bihk,g_bihk);

        dim3 g1(EE/64, BT/64);    // (16, 64)
        sgemm<false><<<g1, 256>>>(p_xq, w1_q,  b1_q,  p_x1q, BT, EE, DIN);
        sgemm<false><<<g1, 256>>>(p_xk, p_w1k, p_b1k, p_x1k, BT, EE, DIN);

        ln_relu<<<BT, 256>>>(p_x1q, gv_q, be_q);
        ln_relu<<<BT, 256>>>(p_x1k, p_gk, p_bek);

        dim3 g2(H3/64, BT/64);    // (96, 64)
        sgemm<true><<<g2, 256>>>(p_x1q, wih_q,  bih_q,  p_xiq, BT, H3, EE);
        sgemm<true><<<g2, 256>>>(p_x1k, p_wihk, p_bihk, p_xik, BT, H3, EE);
    }

    // 4. GRU recurrence (128 sequential steps, both encoders per launch)
    h_init<<<(BB*HH + 255)/256, 256>>>();
    for (int t = 0; t < TT; t++)
        gru_step<<<dim3(HH/32, 2), 256>>>(t, t & 1, whh_q, bhh_q);

    // 5. projection + l2norm -> q_cls, k_cls
    proj_l2<<<dim3(BB, 2), 128>>>(wq, bq, out);

    // 6. queue: copy, metadata (+new_ptrs), scatter k_cls
    queue_copy<<<2816, 256>>>(queues, out);
    queue_meta<<<1, 32>>>(targets, ptrs, out);
    queue_scatter<<<BB*CC, 128>>>(out);
}

// round 4
// speedup vs baseline: 3.0571x; 3.0571x over previous
#include <cuda_runtime.h>
#include <cuda_bf16.h>
#include <math.h>
#include <stdint.h>

// ---------------- problem constants ----------------
#define BB   32
#define TT   128
#define BT   4096          // B*T
#define DIN  4096          // D_RGB + D_FLOW
#define EE   1024
#define HH   2048
#define H3   6144
#define CC   22
#define KQ   1024
#define CDIM 128
#define MOM  0.999f

// output offsets (float32 concat: q_cls, k_cls, new_queues, new_ptrs)
#define OUT_Q      0
#define OUT_K      4096
#define OUT_QUEUE  8192
#define OUT_PTR    (8192 + CC*CDIM*KQ)

#define GS 36   // SMEM row stride (floats) for mma tiles

// ---------------- device scratch (zero-init .bss; allowed) ----------------
__device__ float g_w1qT[EE*DIN];        // w1_q transposed [E][DIN], tf32-rounded
__device__ float g_w1kT[EE*DIN];        // momentum key w1 transposed, tf32-rounded
__device__ float g_wihq[H3*EE];         // wih_q tf32-rounded
__device__ float g_wihk[H3*EE];         // momentum key wih, tf32-rounded
__device__ float g_whhq[H3*HH];         // whh_q tf32-rounded
__device__ float g_whhk[H3*HH];         // momentum key whh, tf32-rounded
__device__ float g_b1k [EE];
__device__ float g_gk  [EE];
__device__ float g_bek [EE];
__device__ float g_bihk[H3];
__device__ float g_bhhk[H3];

__device__ float g_xq  [BT*DIN];        // masked concat (query), tf32-rounded
__device__ float g_xk  [BT*DIN];        // unmasked concat (key), tf32-rounded
__device__ float g_x1q [BT*EE];         // LN+ReLU output, tf32-rounded
__device__ float g_x1k [BT*EE];
__device__ float g_xiq [BT*H3];         // GRU input preacts (fp32)
__device__ float g_xik [BT*H3];

__device__ float g_hq [2][BB*HH];       // fp32 hidden state (ping-pong)
__device__ float g_hk [2][BB*HH];
__device__ float g_hqr[2][BB*HH];       // tf32-rounded copy for mma
__device__ float g_hkr[2][BB*HH];

__device__ int   g_slot[BB*CC];

// ---------------- helpers ----------------
__device__ __forceinline__ float tf32r(float x) {
    uint32_t u;
    asm("cvt.rna.tf32.f32 %0, %1;" : "=r"(u) : "f"(x));
    return __uint_as_float(u);
}
__device__ __forceinline__ void cp16(void* s, const void* g) {
    uint32_t sa = (uint32_t)__cvta_generic_to_shared(s);
    asm volatile("cp.async.cg.shared.global [%0], [%1], 16;" :: "r"(sa), "l"(g));
}
__device__ __forceinline__ void cp_commit() {
    asm volatile("cp.async.commit_group;");
}
template<int N> __device__ __forceinline__ void cp_wait() {
    asm volatile("cp.async.wait_group %0;" :: "n"(N));
}
__device__ __forceinline__ void mma_tf32(float* c, const uint32_t* a, const uint32_t* b) {
    asm volatile("mma.sync.aligned.m16n8k8.row.col.f32.tf32.tf32.f32 "
                 "{%0,%1,%2,%3},{%4,%5,%6,%7},{%8,%9},{%0,%1,%2,%3};"
                 : "+f"(c[0]), "+f"(c[1]), "+f"(c[2]), "+f"(c[3])
                 : "r"(a[0]), "r"(a[1]), "r"(a[2]), "r"(a[3]),
                   "r"(b[0]), "r"(b[1]));
}

// ---------------- prep kernels ----------------
// dst = tf32( fa*sa + fb*sb ), elementwise, float4 grid-stride
__global__ void mix_round(const float4* __restrict__ sa, const float4* __restrict__ sb,
                          float fa, float fb, float4* __restrict__ dst, int n4) {
    for (int i = blockIdx.x*blockDim.x + threadIdx.x; i < n4; i += gridDim.x*blockDim.x) {
        float4 a = sa[i], b = sb[i], o;
        o.x = tf32r(fa*a.x + fb*b.x);
        o.y = tf32r(fa*a.y + fb*b.y);
        o.z = tf32r(fa*a.z + fb*b.z);
        o.w = tf32r(fa*a.w + fb*b.w);
        dst[i] = o;
    }
}
// dst[n][k] = tf32( fa*sa[k][n] + fb*sb[k][n] ), tiled transpose
__global__ __launch_bounds__(256)
void transpose_mix_round(const float* __restrict__ sa, const float* __restrict__ sb,
                         float fa, float fb, float* __restrict__ dst, int Kd, int Nd) {
    __shared__ float sh[32][33];
    int tx = threadIdx.x, ty = threadIdx.y;       // block (32,8)
    int n0 = blockIdx.x*32, k0 = blockIdx.y*32;
#pragma unroll
    for (int i = 0; i < 4; i++) {
        size_t idx = (size_t)(k0 + ty + i*8)*Nd + n0 + tx;
        sh[ty + i*8][tx] = fa*sa[idx] + fb*sb[idx];
    }
    __syncthreads();
#pragma unroll
    for (int i = 0; i < 4; i++)
        dst[(size_t)(n0 + ty + i*8)*Kd + k0 + tx] = tf32r(sh[tx][ty + i*8]);
}
__global__ void mom_vec(const float* b1k, const float* b1q,
                        const float* gk,  const float* gq,
                        const float* bek, const float* beq,
                        const float* bihk,const float* bihq,
                        const float* bhhk,const float* bhhq) {
    int i = blockIdx.x*blockDim.x + threadIdx.x;
    if (i < EE) {
        g_b1k[i] = MOM*b1k[i] + (1.0f-MOM)*b1q[i];
        g_gk [i] = MOM*gk [i] + (1.0f-MOM)*gq [i];
        g_bek[i] = MOM*bek[i] + (1.0f-MOM)*beq[i];
    }
    if (i < H3) {
        g_bihk[i] = MOM*bihk[i] + (1.0f-MOM)*bihq[i];
        g_bhhk[i] = MOM*bhhk[i] + (1.0f-MOM)*bhhq[i];
    }
}

// ---------------- build masked / unmasked concat inputs (tf32-rounded) ----------------
__global__ void build_inputs(const float* __restrict__ rgb, const float* __restrict__ flow,
                             const float* __restrict__ rmask) {
    for (int i = blockIdx.x*blockDim.x + threadIdx.x; i < BT*DIN; i += gridDim.x*blockDim.x) {
        int bt = i >> 12;
        int c  = i & 4095;
        int t  = bt & (TT-1);
        float m = (t == TT-1 || rmask[bt] > 0.25f) ? 1.0f : 0.0f;
        float v = (c < 2048) ? rgb[(size_t)bt*2048 + c] : flow[(size_t)bt*2048 + (c-2048)];
        v = tf32r(v);
        g_xq[i] = v * m;
        g_xk[i] = v;
    }
}

// ---------------- tf32 MMA GEMM: C[M,N] = A[M,K] * B[N,K]^T + bias ----------------
// Operands pre-rounded to tf32. 128x128 block tile, k-tile 32, cp.async 2-stage.
__global__ __launch_bounds__(256)
void gemm_tf32(const float* __restrict__ A, const float* __restrict__ B,
               const float* __restrict__ bias, float* __restrict__ C,
               int M, int N, int K) {
    extern __shared__ float sm[];
    float* As = sm;                    // [2][128][GS]
    float* Bs = sm + 2*128*GS;         // [2][128][GS]

    const int tid = threadIdx.x;
    const int w = tid >> 5, lane = tid & 31;
    const int g = lane >> 2, t4 = lane & 3;
    const int wm = w >> 1, wn = w & 1;
    const int m0 = blockIdx.y * 128, n0 = blockIdx.x * 128;
    const int lr = tid >> 3, lc = (tid & 7) * 4;

    float acc[2][8][4];
#pragma unroll
    for (int mt = 0; mt < 2; mt++)
#pragma unroll
        for (int nt = 0; nt < 8; nt++)
#pragma unroll
            for (int i = 0; i < 4; i++) acc[mt][nt][i] = 0.0f;

    const int KT = K >> 5;
    // prologue: stage 0
    {
        const float* Ag = A + (size_t)m0 * K + lc;
        const float* Bg = B + (size_t)n0 * K + lc;
#pragma unroll
        for (int i = 0; i < 4; i++) {
            cp16(&As[(lr + 32*i)*GS + lc], Ag + (size_t)(lr + 32*i)*K);
            cp16(&Bs[(lr + 32*i)*GS + lc], Bg + (size_t)(lr + 32*i)*K);
        }
        cp_commit();
    }
    for (int kt = 0; kt < KT; kt++) {
        if (kt + 1 < KT) {
            int s = (kt + 1) & 1, k0 = (kt + 1) << 5;
            const float* Ag = A + (size_t)m0 * K + k0 + lc;
            const float* Bg = B + (size_t)n0 * K + k0 + lc;
#pragma unroll
            for (int i = 0; i < 4; i++) {
                cp16(&As[s*128*GS + (lr + 32*i)*GS + lc], Ag + (size_t)(lr + 32*i)*K);
                cp16(&Bs[s*128*GS + (lr + 32*i)*GS + lc], Bg + (size_t)(lr + 32*i)*K);
            }
            cp_commit();
            cp_wait<1>();
        } else {
            cp_wait<0>();
        }
        __syncthreads();
        const float* as = As + (kt & 1)*128*GS;
        const float* bs = Bs + (kt & 1)*128*GS;
#pragma unroll
        for (int k8 = 0; k8 < 4; k8++) {
            int kc = k8*8 + t4;
            uint32_t a[2][4], b[8][2];
#pragma unroll
            for (int mt = 0; mt < 2; mt++) {
                int mr = wm*32 + mt*16 + g;
                a[mt][0] = __float_as_uint(as[mr*GS + kc]);
                a[mt][1] = __float_as_uint(as[(mr+8)*GS + kc]);
                a[mt][2] = __float_as_uint(as[mr*GS + kc + 4]);
                a[mt][3] = __float_as_uint(as[(mr+8)*GS + kc + 4]);
            }
#pragma unroll
            for (int nt = 0; nt < 8; nt++) {
                int nr = wn*64 + nt*8 + g;
                b[nt][0] = __float_as_uint(bs[nr*GS + kc]);
                b[nt][1] = __float_as_uint(bs[nr*GS + kc + 4]);
            }
#pragma unroll
            for (int mt = 0; mt < 2; mt++)
#pragma unroll
                for (int nt = 0; nt < 8; nt++)
                    mma_tf32(acc[mt][nt], a[mt], b[nt]);
        }
        __syncthreads();
    }
    // epilogue: + bias
#pragma unroll
    for (int mt = 0; mt < 2; mt++)
#pragma unroll
        for (int nt = 0; nt < 8; nt++) {
            int col = n0 + wn*64 + nt*8 + 2*t4;
            float b0 = bias[col], b1 = bias[col+1];
            int r0 = m0 + wm*32 + mt*16 + g;
            float2 v0 = make_float2(acc[mt][nt][0] + b0, acc[mt][nt][1] + b1);
            float2 v1 = make_float2(acc[mt][nt][2] + b0, acc[mt][nt][3] + b1);
            *(float2*)(C + (size_t)r0*N + col)     = v0;
            *(float2*)(C + (size_t)(r0+8)*N + col) = v1;
        }
}

// ---------------- LayerNorm + ReLU (in place), rows of EE=1024, tf32-rounded out ---
__global__ __launch_bounds__(256)
void ln_relu(float* __restrict__ x, const float* __restrict__ g, const float* __restrict__ be) {
    int row = blockIdx.x;
    int tid = threadIdx.x;
    float4* xr = (float4*)(x + (size_t)row * EE);
    float4 v = xr[tid];
    float s  = v.x + v.y + v.z + v.w;
    float ss = v.x*v.x + v.y*v.y + v.z*v.z + v.w*v.w;
#pragma unroll
    for (int o = 16; o; o >>= 1) {
        s  += __shfl_xor_sync(0xffffffffu, s,  o);
        ss += __shfl_xor_sync(0xffffffffu, ss, o);
    }
    __shared__ float sh_s[8], sh_ss[8];
    if ((tid & 31) == 0) { sh_s[tid >> 5] = s; sh_ss[tid >> 5] = ss; }
    __syncthreads();
    float S = 0.0f, SS = 0.0f;
#pragma unroll
    for (int w = 0; w < 8; w++) { S += sh_s[w]; SS += sh_ss[w]; }
    float mu   = S * (1.0f / EE);
    float var  = SS * (1.0f / EE) - mu * mu;
    float rstd = rsqrtf(var + 1e-5f);
    int c = tid * 4;
    float4 gg = *(const float4*)(g  + c);
    float4 bb = *(const float4*)(be + c);
    float4 y;
    y.x = tf32r(fmaxf((v.x - mu) * rstd * gg.x + bb.x, 0.0f));
    y.y = tf32r(fmaxf((v.y - mu) * rstd * gg.y + bb.y, 0.0f));
    y.z = tf32r(fmaxf((v.z - mu) * rstd * gg.z + bb.z, 0.0f));
    y.w = tf32r(fmaxf((v.w - mu) * rstd * gg.w + bb.w, 0.0f));
    xr[tid] = y;
}

// ---------------- init hidden state ----------------
__global__ void h_init() {
    int i = blockIdx.x*blockDim.x + threadIdx.x;
    if (i < BB*HH) {
        g_hq[0][i] = 0.0f; g_hk[0][i] = 0.0f;
        g_hqr[0][i] = 0.0f; g_hkr[0][i] = 0.0f;
    }
}

// ---------------- one GRU step via tf32 MMA ----------------
// grid (HH/32, 2 encoders), 128 threads (4 warps). Block computes
// C[32, 96] = h[32,2048] @ whh[{r,z,n} rows j0..j0+31, 2048]^T, then gates.
__global__ __launch_bounds__(128)
void gru_step_mma(int t, int par, const float* __restrict__ bhh_qp) {
    extern __shared__ float sm[];
    float* Hs = sm;                         // [2][32][GS]
    float* Ws = sm + 2*32*GS;               // [2][96][GS]
    float* Cs = sm + 2*32*GS + 2*96*GS;     // [32][97]

    const int enc = blockIdx.y;
    const int j0  = blockIdx.x * 32;
    const int tid = threadIdx.x;
    const int w = tid >> 5, lane = tid & 31;
    const int g = lane >> 2, t4 = lane & 3;

    const float* whh   = enc ? g_whhk : g_whhq;
    const float* bhh   = enc ? g_bhhk : bhh_qp;
    const float* xi    = enc ? g_xik  : g_xiq;
    const float* holdf = enc ? g_hk [par] : g_hq [par];
    const float* holdr = enc ? g_hkr[par] : g_hqr[par];
    float* newf = enc ? g_hk [par ^ 1] : g_hq [par ^ 1];
    float* newr = enc ? g_hkr[par ^ 1] : g_hqr[par ^ 1];

    float acc[2][3][4];
#pragma unroll
    for (int mt = 0; mt < 2; mt++)
#pragma unroll
        for (int nt = 0; nt < 3; nt++)
#pragma unroll
            for (int i = 0; i < 4; i++) acc[mt][nt][i] = 0.0f;

    // stage loaders
    auto loadStage = [&](int s, int k0) {
#pragma unroll
        for (int l = 0; l < 2; l++) {              // H: 32x32
            int idx = tid + l*128;
            int row = idx >> 3, c4 = (idx & 7)*4;
            cp16(&Hs[s*32*GS + row*GS + c4], holdr + (size_t)row*HH + k0 + c4);
        }
#pragma unroll
        for (int l = 0; l < 6; l++) {              // W: 96x32
            int idx = tid + l*128;
            int row = idx >> 3, c4 = (idx & 7)*4;
            int n = (row >> 5)*HH + j0 + (row & 31);
            cp16(&Ws[s*96*GS + row*GS + c4], whh + (size_t)n*HH + k0 + c4);
        }
        cp_commit();
    };

    loadStage(0, 0);
    const int KT = HH / 32;   // 64
    for (int kt = 0; kt < KT; kt++) {
        if (kt + 1 < KT) { loadStage((kt+1) & 1, (kt+1)*32); cp_wait<1>(); }
        else             { cp_wait<0>(); }
        __syncthreads();
        const float* hs = Hs + (kt & 1)*32*GS;
        const float* ws = Ws + (kt & 1)*96*GS;
#pragma unroll
        for (int k8 = 0; k8 < 4; k8++) {
            int kc = k8*8 + t4;
            uint32_t a[2][4], b[3][2];
#pragma unroll
            for (int mt = 0; mt < 2; mt++) {
                int mr = mt*16 + g;
                a[mt][0] = __float_as_uint(hs[mr*GS + kc]);
                a[mt][1] = __float_as_uint(hs[(mr+8)*GS + kc]);
                a[mt][2] = __float_as_uint(hs[mr*GS + kc + 4]);
                a[mt][3] = __float_as_uint(hs[(mr+8)*GS + kc + 4]);
            }
#pragma unroll
            for (int nt = 0; nt < 3; nt++) {
                int nr = w*24 + nt*8 + g;
                b[nt][0] = __float_as_uint(ws[nr*GS + kc]);
                b[nt][1] = __float_as_uint(ws[nr*GS + kc + 4]);
            }
#pragma unroll
            for (int mt = 0; mt < 2; mt++)
#pragma unroll
                for (int nt = 0; nt < 3; nt++)
                    mma_tf32(acc[mt][nt], a[mt], b[nt]);
        }
        __syncthreads();
    }

    // stage accumulators: Cs[b][c], c = gate*32 + j_local
#pragma unroll
    for (int mt = 0; mt < 2; mt++)
#pragma unroll
        for (int nt = 0; nt < 3; nt++) {
            int col = w*24 + nt*8 + 2*t4;
            int r0 = mt*16 + g;
            Cs[r0*97 + col]       = acc[mt][nt][0];
            Cs[r0*97 + col + 1]   = acc[mt][nt][1];
            Cs[(r0+8)*97 + col]   = acc[mt][nt][2];
            Cs[(r0+8)*97 + col+1] = acc[mt][nt][3];
        }
    __syncthreads();

    // gates: each thread 8 (b, j) pairs; consecutive lanes -> consecutive j
#pragma unroll
    for (int l = 0; l < 8; l++) {
        int b = l*4 + w;
        int j = lane;
        float pr = Cs[b*97 + j]      + bhh[j0 + j];
        float pz = Cs[b*97 + 32 + j] + bhh[HH + j0 + j];
        float pn = Cs[b*97 + 64 + j] + bhh[2*HH + j0 + j];
        const float* xir = xi + ((size_t)b*TT + t)*H3 + j0 + j;
        float r  = 1.0f / (1.0f + expf(-(xir[0]    + pr)));
        float z  = 1.0f / (1.0f + expf(-(xir[2048] + pz)));
        float nn = tanhf(xir[4096] + r * pn);
        float hp = holdf[(size_t)b*HH + j0 + j];
        float hv = (1.0f - z) * nn + z * hp;
        newf[(size_t)b*HH + j0 + j] = hv;
        newr[(size_t)b*HH + j0 + j] = tf32r(hv);
    }
}

// ---------------- projection + l2norm: out[enc*4096 + b*128 + d] ----------------
__global__ __launch_bounds__(128)
void proj_l2(const float* __restrict__ wq, const float* __restrict__ bq, float* __restrict__ out) {
    const int enc = blockIdx.y, b = blockIdx.x, d = threadIdx.x;
    const float* h = (enc ? g_hk[0] : g_hq[0]) + (size_t)b * HH;
    float acc = bq[d];
#pragma unroll 4
    for (int k = 0; k < HH; k++)
        acc = fmaf(fmaxf(h[k], 0.0f), wq[(size_t)k*CDIM + d], acc);
    __shared__ float sh[128];
    sh[d] = acc * acc;
    __syncthreads();
#pragma unroll
    for (int o = 64; o; o >>= 1) { if (d < o) sh[d] += sh[d + o]; __syncthreads(); }
    out[enc*4096 + b*CDIM + d] = acc * rsqrtf(sh[0]);
}

// ---------------- queue: copy, slot metadata, scatter, ptrs ----------------
__global__ void queue_copy(const float* __restrict__ q, float* __restrict__ out) {
    const float4* src = (const float4*)q;
    float4* dst = (float4*)(out + OUT_QUEUE);
    for (int i = blockIdx.x*blockDim.x + threadIdx.x; i < (CC*CDIM*KQ)/4; i += gridDim.x*blockDim.x)
        dst[i] = src[i];
}
__global__ void queue_meta(const float* __restrict__ targets, const int* __restrict__ ptrs,
                           float* __restrict__ out) {
    int c = threadIdx.x;
    if (c < CC) {
        int cnt = 0;
        int p = ptrs[c];
        for (int b = 0; b < BB; b++) {
            if (targets[b*CC + c] > 0.5f) { g_slot[b*CC + c] = (p + cnt) % KQ; cnt++; }
            else                            g_slot[b*CC + c] = -1;
        }
        out[OUT_PTR + c] = (float)((p + cnt) % KQ);
    }
}
__global__ __launch_bounds__(128)
void queue_scatter(float* __restrict__ out) {
    int bc = blockIdx.x;
    int b = bc / CC, c = bc % CC;
    int s = g_slot[b*CC + c];
    if (s < 0) return;
    int d = threadIdx.x;
    float v = out[OUT_K + b*CDIM + d];
    out[OUT_QUEUE + (size_t)c*CDIM*KQ + (size_t)d*KQ + s] = v;
}

// ---------------- host launch ----------------
extern "C" void kernel_launch(void* const* d_in, const int* in_sizes, int n_in,
                              void* d_out, int out_size) {
    const float* rgb    = (const float*)d_in[0];
    const float* flow   = (const float*)d_in[1];
    const float* rmask  = (const float*)d_in[2];
    const float* targets= (const float*)d_in[3];
    const float* w1_q   = (const float*)d_in[4];
    const float* b1_q   = (const float*)d_in[5];
    const float* gv_q   = (const float*)d_in[6];
    const float* be_q   = (const float*)d_in[7];
    const float* wih_q  = (const float*)d_in[8];
    const float* whh_q  = (const float*)d_in[9];
    const float* bih_q  = (const float*)d_in[10];
    const float* bhh_q  = (const float*)d_in[11];
    const float* w1_k   = (const float*)d_in[12];
    const float* b1_k   = (const float*)d_in[13];
    const float* gv_k   = (const float*)d_in[14];
    const float* be_k   = (const float*)d_in[15];
    const float* wih_k  = (const float*)d_in[16];
    const float* whh_k  = (const float*)d_in[17];
    const float* bih_k  = (const float*)d_in[18];
    const float* bhh_k  = (const float*)d_in[19];
    const float* wq     = (const float*)d_in[20];
    const float* bq     = (const float*)d_in[21];
    int ptrs_idx = (in_sizes[22] == CC) ? 22 : 23;
    int queues_idx = 45 - ptrs_idx;
    const int*   ptrs   = (const int*)d_in[ptrs_idx];
    const float* queues = (const float*)d_in[queues_idx];
    float* out = (float*)d_out;

    const int GEMM_SMEM = 2 * 2 * 128 * GS * 4;                        // 73728
    const int GRU_SMEM  = (2*32*GS + 2*96*GS + 32*97) * 4;             // 49280
    cudaFuncSetAttribute(gemm_tf32,    cudaFuncAttributeMaxDynamicSharedMemorySize, GEMM_SMEM);
    cudaFuncSetAttribute(gru_step_mma, cudaFuncAttributeMaxDynamicSharedMemorySize, GRU_SMEM);

    float *p_w1qT, *p_w1kT, *p_wihq, *p_wihk, *p_whhq, *p_whhk;
    float *p_xq, *p_xk, *p_x1q, *p_x1k, *p_xiq, *p_xik;
    float *p_b1k, *p_gk, *p_bek, *p_bihk;
    cudaGetSymbolAddress((void**)&p_w1qT, g_w1qT);
    cudaGetSymbolAddress((void**)&p_w1kT, g_w1kT);
    cudaGetSymbolAddress((void**)&p_wihq, g_wihq);
    cudaGetSymbolAddress((void**)&p_wihk, g_wihk);
    cudaGetSymbolAddress((void**)&p_whhq, g_whhq);
    cudaGetSymbolAddress((void**)&p_whhk, g_whhk);
    cudaGetSymbolAddress((void**)&p_xq,   g_xq);
    cudaGetSymbolAddress((void**)&p_xk,   g_xk);
    cudaGetSymbolAddress((void**)&p_x1q,  g_x1q);
    cudaGetSymbolAddress((void**)&p_x1k,  g_x1k);
    cudaGetSymbolAddress((void**)&p_xiq,  g_xiq);
    cudaGetSymbolAddress((void**)&p_xik,  g_xik);
    cudaGetSymbolAddress((void**)&p_b1k,  g_b1k);
    cudaGetSymbolAddress((void**)&p_gk,   g_gk);
    cudaGetSymbolAddress((void**)&p_bek,  g_bek);
    cudaGetSymbolAddress((void**)&p_bihk, g_bihk);

    // 1. weight prep: transpose / momentum / tf32 rounding
    {
        dim3 tb(32, 8);
        dim3 tg(EE/32, DIN/32);   // (32, 128)
        transpose_mix_round<<<tg, tb>>>(w1_q, w1_q, 1.0f, 0.0f, p_w1qT, DIN, EE);
        transpose_mix_round<<<tg, tb>>>(w1_k, w1_q, MOM, 1.0f - MOM, p_w1kT, DIN, EE);
        mix_round<<<2048, 256>>>((const float4*)wih_q, (const float4*)wih_q, 1.0f, 0.0f,
                                 (float4*)p_wihq, (H3*EE)/4);
        mix_round<<<2048, 256>>>((const float4*)wih_k, (const float4*)wih_q, MOM, 1.0f - MOM,
                                 (float4*)p_wihk, (H3*EE)/4);
        mix_round<<<4096, 256>>>((const float4*)whh_q, (const float4*)whh_q, 1.0f, 0.0f,
                                 (float4*)p_whhq, (H3*HH)/4);
        mix_round<<<4096, 256>>>((const float4*)whh_k, (const float4*)whh_q, MOM, 1.0f - MOM,
                                 (float4*)p_whhk, (H3*HH)/4);
        mom_vec<<<(H3 + 255)/256, 256>>>(b1_k, b1_q, gv_k, gv_q, be_k, be_q,
                                         bih_k, bih_q, bhh_k, bhh_q);
    }

    // 2. build inputs (tf32-rounded)
    build_inputs<<<16384, 256>>>(rgb, flow, rmask);

    // 3. GEMM1 -> LN/ReLU -> GEMM2 (all tf32 tensor cores)
    {
        dim3 g1(EE/128, BT/128);    // (8, 32)
        gemm_tf32<<<g1, 256, GEMM_SMEM>>>(p_xq, p_w1qT, b1_q,  p_x1q, BT, EE, DIN);
        gemm_tf32<<<g1, 256, GEMM_SMEM>>>(p_xk, p_w1kT, p_b1k, p_x1k, BT, EE, DIN);

        ln_relu<<<BT, 256>>>(p_x1q, gv_q, be_q);
        ln_relu<<<BT, 256>>>(p_x1k, p_gk, p_bek);

        dim3 g2(H3/128, BT/128);    // (48, 32)
        gemm_tf32<<<g2, 256, GEMM_SMEM>>>(p_x1q, p_wihq, bih_q,  p_xiq, BT, H3, EE);
        gemm_tf32<<<g2, 256, GEMM_SMEM>>>(p_x1k, p_wihk, p_bihk, p_xik, BT, H3, EE);
    }

    // 4. GRU recurrence (128 steps, tensor-core hh GEMM + fused gates)
    h_init<<<(BB*HH + 255)/256, 256>>>();
    for (int t = 0; t < TT; t++)
        gru_step_mma<<<dim3(HH/32, 2), 128, GRU_SMEM>>>(t, t & 1, bhh_q);

    // 5. projection + l2norm -> q_cls, k_cls
    proj_l2<<<dim3(BB, 2), 128>>>(wq, bq, out);

    // 6. queue: copy, metadata (+new_ptrs), scatter k_cls
    queue_copy<<<2816, 256>>>(queues, out);
    queue_meta<<<1, 32>>>(targets, ptrs, out);
    queue_scatter<<<BB*CC, 128>>>(out);
}

// round 8
// speedup vs baseline: 4.7473x; 1.5529x over previous
#include <cuda_runtime.h>
#include <cuda_fp16.h>
#include <math.h>
#include <stdint.h>

// ---------------- problem constants ----------------
#define BB   32
#define TT   128
#define BT   4096          // B*T
#define DIN  4096          // D_RGB + D_FLOW
#define EE   1024
#define HH   2048
#define H3   6144
#define CC   22
#define KQ   1024
#define CDIM 128
#define MOM  0.999f

// output offsets (float32 concat: q_cls, k_cls, new_queues, new_ptrs)
#define OUT_Q      0
#define OUT_K      4096
#define OUT_QUEUE  8192
#define OUT_PTR    (8192 + CC*CDIM*KQ)

#define HS 40   // SMEM row stride in halves (80B): 16B-aligned rows, conflict-free frags

// ---------------- device scratch (zero-init .bss; allowed) ----------------
__device__ __align__(16) __half g_w1qT[EE*DIN];   // w1_q^T [E][DIN] fp16
__device__ __align__(16) __half g_w1kT[EE*DIN];   // momentum key w1^T fp16
__device__ __align__(16) __half g_wihq[H3*EE];
__device__ __align__(16) __half g_wihk[H3*EE];
__device__ __align__(16) __half g_whhq[H3*HH];
__device__ __align__(16) __half g_whhk[H3*HH];
__device__ float  g_b1k [EE];
__device__ float  g_gk  [EE];
__device__ float  g_bek [EE];
__device__ float  g_bihk[H3];
__device__ float  g_bhhk[H3];

__device__ __align__(16) __half g_xq  [BT*DIN];   // masked concat (query) fp16
__device__ __align__(16) __half g_xk  [BT*DIN];   // unmasked concat (key) fp16
__device__ float  g_y1q [BT*EE];                  // GEMM1 out fp32
__device__ float  g_y1k [BT*EE];
__device__ __align__(16) __half g_x1q [BT*EE];    // LN+ReLU out fp16
__device__ __align__(16) __half g_x1k [BT*EE];
__device__ float  g_xiq [BT*H3];                  // GRU input preacts fp32
__device__ float  g_xik [BT*H3];

__device__ float  g_hq [2][BB*HH];                // fp32 hidden state (ping-pong)
__device__ float  g_hk [2][BB*HH];
__device__ __align__(16) __half g_hqh[2][BB*HH];  // fp16 copy for mma
__device__ __align__(16) __half g_hkh[2][BB*HH];

__device__ int    g_slot[BB*CC];

// ---------------- helpers ----------------
__device__ __forceinline__ void cp16(void* s, const void* g) {
    uint32_t sa = (uint32_t)__cvta_generic_to_shared(s);
    asm volatile("cp.async.cg.shared.global [%0], [%1], 16;" :: "r"(sa), "l"(g));
}
__device__ __forceinline__ void cp_commit() {
    asm volatile("cp.async.commit_group;");
}
template<int N> __device__ __forceinline__ void cp_wait() {
    asm volatile("cp.async.wait_group %0;" :: "n"(N));
}
__device__ __forceinline__ void mma_fp16(float* c, const uint32_t* a, const uint32_t* b) {
    asm volatile("mma.sync.aligned.m16n8k16.row.col.f32.f16.f16.f32 "
                 "{%0,%1,%2,%3},{%4,%5,%6,%7},{%8,%9},{%0,%1,%2,%3};"
                 : "+f"(c[0]), "+f"(c[1]), "+f"(c[2]), "+f"(c[3])
                 : "r"(a[0]), "r"(a[1]), "r"(a[2]), "r"(a[3]),
                   "r"(b[0]), "r"(b[1]));
}
__device__ __forceinline__ uint32_t pack2(float a, float b) {
    __half2 h = __floats2half2_rn(a, b);
    return *(uint32_t*)&h;
}

// ---------------- prep kernels ----------------
// dst_half = half( fa*sa + fb*sb ), float4-vectorized
__global__ void mix_half(const float4* __restrict__ sa, const float4* __restrict__ sb,
                         float fa, float fb, uint2* __restrict__ dst, int n4) {
    for (int i = blockIdx.x*blockDim.x + threadIdx.x; i < n4; i += gridDim.x*blockDim.x) {
        float4 a = sa[i], b = sb[i];
        uint2 o;
        o.x = pack2(fa*a.x + fb*b.x, fa*a.y + fb*b.y);
        o.y = pack2(fa*a.z + fb*b.z, fa*a.w + fb*b.w);
        dst[i] = o;
    }
}
// dst[n][k] = half( fa*sa[k][n] + fb*sb[k][n] ), tiled transpose
__global__ __launch_bounds__(256)
void transpose_mix_half(const float* __restrict__ sa, const float* __restrict__ sb,
                        float fa, float fb, __half* __restrict__ dst, int Kd, int Nd) {
    __shared__ float sh[32][33];
    int tx = threadIdx.x, ty = threadIdx.y;       // block (32,8)
    int n0 = blockIdx.x*32, k0 = blockIdx.y*32;
#pragma unroll
    for (int i = 0; i < 4; i++) {
        size_t idx = (size_t)(k0 + ty + i*8)*Nd + n0 + tx;
        sh[ty + i*8][tx] = fa*sa[idx] + fb*sb[idx];
    }
    __syncthreads();
#pragma unroll
    for (int i = 0; i < 4; i++)
        dst[(size_t)(n0 + ty + i*8)*Kd + k0 + tx] = __float2half(sh[tx][ty + i*8]);
}
__global__ void mom_vec(const float* b1k, const float* b1q,
                        const float* gk,  const float* gq,
                        const float* bek, const float* beq,
                        const float* bihk,const float* bihq,
                        const float* bhhk,const float* bhhq) {
    int i = blockIdx.x*blockDim.x + threadIdx.x;
    if (i < EE) {
        g_b1k[i] = MOM*b1k[i] + (1.0f-MOM)*b1q[i];
        g_gk [i] = MOM*gk [i] + (1.0f-MOM)*gq [i];
        g_bek[i] = MOM*bek[i] + (1.0f-MOM)*beq[i];
    }
    if (i < H3) {
        g_bihk[i] = MOM*bihk[i] + (1.0f-MOM)*bihq[i];
        g_bhhk[i] = MOM*bhhk[i] + (1.0f-MOM)*bhhq[i];
    }
}

// ---------------- build masked / unmasked concat inputs (fp16) ----------------
__global__ void build_inputs(const float4* __restrict__ rgb, const float4* __restrict__ flow,
                             const float* __restrict__ rmask) {
    // i4 indexes groups of 4 elements of the [BT][4096] concat
    uint2* xq = (uint2*)g_xq;
    uint2* xk = (uint2*)g_xk;
    for (int i4 = blockIdx.x*blockDim.x + threadIdx.x; i4 < (BT*DIN)/4; i4 += gridDim.x*blockDim.x) {
        int bt = i4 >> 10;
        int c4 = i4 & 1023;           // group-of-4 within 4096
        int t  = bt & (TT-1);
        float m = (t == TT-1 || rmask[bt] > 0.25f) ? 1.0f : 0.0f;
        float4 v = (c4 < 512) ? rgb[(size_t)bt*512 + c4] : flow[(size_t)bt*512 + (c4-512)];
        uint2 ok; ok.x = pack2(v.x, v.y); ok.y = pack2(v.z, v.w);
        uint2 oq; oq.x = pack2(v.x*m, v.y*m); oq.y = pack2(v.z*m, v.w*m);
        xq[i4] = oq;
        xk[i4] = ok;
    }
}

// ---------------- fp16 MMA GEMM: C[M,N] = A[M,K]h * B[N,K]h^T + bias ----------------
// 128x128 block tile, k-tile 32 halves, cp.async 2-stage, 8 warps.
__global__ __launch_bounds__(256)
void gemm_fp16(const __half* __restrict__ A, const __half* __restrict__ B,
               const float* __restrict__ bias, float* __restrict__ C,
               int M, int N, int K) {
    extern __shared__ __half smh[];
    __half* As = smh;                  // [2][128][HS]
    __half* Bs = smh + 2*128*HS;       // [2][128][HS]

    const int tid = threadIdx.x;
    const int w = tid >> 5, lane = tid & 31;
    const int g = lane >> 2, t4 = lane & 3;
    const int wm = w >> 1, wn = w & 1;
    const int m0 = blockIdx.y * 128, n0 = blockIdx.x * 128;
    const int lr = tid >> 1, lseg = (tid & 1) * 2;

    float acc[2][8][4];
#pragma unroll
    for (int mt = 0; mt < 2; mt++)
#pragma unroll
        for (int nt = 0; nt < 8; nt++)
#pragma unroll
            for (int i = 0; i < 4; i++) acc[mt][nt][i] = 0.0f;

    auto loadStage = [&](int s, int k0) {
        const __half* Ag = A + (size_t)m0 * K + k0;
        const __half* Bg = B + (size_t)n0 * K + k0;
        __half* as = As + s*128*HS;
        __half* bs = Bs + s*128*HS;
#pragma unroll
        for (int i = 0; i < 2; i++) {
            int seg = lseg + i;                       // 0..3
            cp16(&as[lr*HS + seg*8], Ag + (size_t)lr*K + seg*8);
            cp16(&bs[lr*HS + seg*8], Bg + (size_t)lr*K + seg*8);
        }
        cp_commit();
    };

    const int KT = K >> 5;
    loadStage(0, 0);
    for (int kt = 0; kt < KT; kt++) {
        if (kt + 1 < KT) { loadStage((kt+1) & 1, (kt+1) << 5); cp_wait<1>(); }
        else             { cp_wait<0>(); }
        __syncthreads();
        const __half* as = As + (kt & 1)*128*HS;
        const __half* bs = Bs + (kt & 1)*128*HS;
#pragma unroll
        for (int ks = 0; ks < 2; ks++) {
            int kc = ks*16 + 2*t4;
            uint32_t a[2][4], b[8][2];
#pragma unroll
            for (int mt = 0; mt < 2; mt++) {
                int mr = wm*32 + mt*16 + g;
                a[mt][0] = *(const uint32_t*)&as[mr*HS + kc];
                a[mt][1] = *(const uint32_t*)&as[(mr+8)*HS + kc];
                a[mt][2] = *(const uint32_t*)&as[mr*HS + kc + 8];
                a[mt][3] = *(const uint32_t*)&as[(mr+8)*HS + kc + 8];
            }
#pragma unroll
            for (int nt = 0; nt < 8; nt++) {
                int nr = wn*64 + nt*8 + g;
                b[nt][0] = *(const uint32_t*)&bs[nr*HS + kc];
                b[nt][1] = *(const uint32_t*)&bs[nr*HS + kc + 8];
            }
#pragma unroll
            for (int mt = 0; mt < 2; mt++)
#pragma unroll
                for (int nt = 0; nt < 8; nt++)
                    mma_fp16(acc[mt][nt], a[mt], b[nt]);
        }
        __syncthreads();
    }
    // epilogue: + bias
#pragma unroll
    for (int mt = 0; mt < 2; mt++)
#pragma unroll
        for (int nt = 0; nt < 8; nt++) {
            int col = n0 + wn*64 + nt*8 + 2*t4;
            float b0 = bias[col], b1 = bias[col+1];
            int r0 = m0 + wm*32 + mt*16 + g;
            float2 v0 = make_float2(acc[mt][nt][0] + b0, acc[mt][nt][1] + b1);
            float2 v1 = make_float2(acc[mt][nt][2] + b0, acc[mt][nt][3] + b1);
            *(float2*)(C + (size_t)r0*N + col)     = v0;
            *(float2*)(C + (size_t)(r0+8)*N + col) = v1;
        }
}

// ---------------- LayerNorm + ReLU, fp32 in -> fp16 out, rows of EE=1024 ----------
__global__ __launch_bounds__(256)
void ln_relu(const float* __restrict__ x, __half* __restrict__ xo,
             const float* __restrict__ g, const float* __restrict__ be) {
    int row = blockIdx.x;
    int tid = threadIdx.x;
    const float4* xr = (const float4*)(x + (size_t)row * EE);
    float4 v = xr[tid];
    float s  = v.x + v.y + v.z + v.w;
    float ss = v.x*v.x + v.y*v.y + v.z*v.z + v.w*v.w;
#pragma unroll
    for (int o = 16; o; o >>= 1) {
        s  += __shfl_xor_sync(0xffffffffu, s,  o);
        ss += __shfl_xor_sync(0xffffffffu, ss, o);
    }
    __shared__ float sh_s[8], sh_ss[8];
    if ((tid & 31) == 0) { sh_s[tid >> 5] = s; sh_ss[tid >> 5] = ss; }
    __syncthreads();
    float S = 0.0f, SS = 0.0f;
#pragma unroll
    for (int w = 0; w < 8; w++) { S += sh_s[w]; SS += sh_ss[w]; }
    float mu   = S * (1.0f / EE);
    float var  = SS * (1.0f / EE) - mu * mu;
    float rstd = rsqrtf(var + 1e-5f);
    int c = tid * 4;
    float4 gg = *(const float4*)(g  + c);
    float4 bb = *(const float4*)(be + c);
    uint2 o;
    o.x = pack2(fmaxf((v.x - mu) * rstd * gg.x + bb.x, 0.0f),
                fmaxf((v.y - mu) * rstd * gg.y + bb.y, 0.0f));
    o.y = pack2(fmaxf((v.z - mu) * rstd * gg.z + bb.z, 0.0f),
                fmaxf((v.w - mu) * rstd * gg.w + bb.w, 0.0f));
    ((uint2*)(xo + (size_t)row * EE))[tid] = o;
}

// ---------------- init hidden state ----------------
__global__ void h_init() {
    int i = blockIdx.x*blockDim.x + threadIdx.x;
    if (i < BB*HH) {
        g_hq[0][i] = 0.0f; g_hk[0][i] = 0.0f;
        g_hqh[0][i] = __float2half(0.0f); g_hkh[0][i] = __float2half(0.0f);
    }
}

// ---------------- one GRU step via fp16 MMA ----------------
// grid (HH/32, 2 encoders), 128 threads (4 warps). Block computes
// C[32, 96] = h[32,2048] @ whh[{r,z,n} rows j0..j0+31, 2048]^T, then gates.
__global__ __launch_bounds__(128)
void gru_step_mma(int t, int par, const float* __restrict__ bhh_qp) {
    extern __shared__ __half smh[];
    __half* Hsm = smh;                        // [2][32][HS]
    __half* Wsm = smh + 2*32*HS;              // [2][96][HS]
    float*  Cs  = (float*)(smh + 2*32*HS + 2*96*HS);   // [32][97]

    const int enc = blockIdx.y;
    const int j0  = blockIdx.x * 32;
    const int tid = threadIdx.x;
    const int w = tid >> 5, lane = tid & 31;
    const int g = lane >> 2, t4 = lane & 3;

    const __half* whh  = enc ? g_whhk : g_whhq;
    const float*  bhh  = enc ? g_bhhk : bhh_qp;
    const float*  xi   = enc ? g_xik  : g_xiq;
    const float*  holdf= enc ? g_hk [par] : g_hq [par];
    const __half* holdh= enc ? g_hkh[par] : g_hqh[par];
    float*  newf = enc ? g_hk [par ^ 1] : g_hq [par ^ 1];
    __half* newh = enc ? g_hkh[par ^ 1] : g_hqh[par ^ 1];

    float acc[2][3][4];
#pragma unroll
    for (int mt = 0; mt < 2; mt++)
#pragma unroll
        for (int nt = 0; nt < 3; nt++)
#pragma unroll
            for (int i = 0; i < 4; i++) acc[mt][nt][i] = 0.0f;

    auto loadStage = [&](int s, int k0) {
        __half* hs = Hsm + s*32*HS;
        __half* ws = Wsm + s*96*HS;
        {   // H: 32 rows x 32 halves = 128 segs; 1 per thread
            int row = tid >> 2, seg = tid & 3;
            cp16(&hs[row*HS + seg*8], holdh + (size_t)row*HH + k0 + seg*8);
        }
#pragma unroll
        for (int l = 0; l < 3; l++) {             // W: 96 x 32 = 384 segs; 3 per thread
            int idx = tid + l*128;
            int row = idx >> 2, seg = idx & 3;
            int n = (row >> 5)*HH + j0 + (row & 31);
            cp16(&ws[row*HS + seg*8], whh + (size_t)n*HH + k0 + seg*8);
        }
        cp_commit();
    };

    loadStage(0, 0);
    const int KT = HH / 32;   // 64
    for (int kt = 0; kt < KT; kt++) {
        if (kt + 1 < KT) { loadStage((kt+1) & 1, (kt+1)*32); cp_wait<1>(); }
        else             { cp_wait<0>(); }
        __syncthreads();
        const __half* hs = Hsm + (kt & 1)*32*HS;
        const __half* ws = Wsm + (kt & 1)*96*HS;
#pragma unroll
        for (int ks = 0; ks < 2; ks++) {
            int kc = ks*16 + 2*t4;
            uint32_t a[2][4], b[3][2];
#pragma unroll
            for (int mt = 0; mt < 2; mt++) {
                int mr = mt*16 + g;
                a[mt][0] = *(const uint32_t*)&hs[mr*HS + kc];
                a[mt][1] = *(const uint32_t*)&hs[(mr+8)*HS + kc];
                a[mt][2] = *(const uint32_t*)&hs[mr*HS + kc + 8];
                a[mt][3] = *(const uint32_t*)&hs[(mr+8)*HS + kc + 8];
            }
#pragma unroll
            for (int nt = 0; nt < 3; nt++) {
                int nr = w*24 + nt*8 + g;
                b[nt][0] = *(const uint32_t*)&ws[nr*HS + kc];
                b[nt][1] = *(const uint32_t*)&ws[nr*HS + kc + 8];
            }
#pragma unroll
            for (int mt = 0; mt < 2; mt++)
#pragma unroll
                for (int nt = 0; nt < 3; nt++)
                    mma_fp16(acc[mt][nt], a[mt], b[nt]);
        }
        __syncthreads();
    }

    // stage accumulators: Cs[b][c], c = gate*32 + j_local
#pragma unroll
    for (int mt = 0; mt < 2; mt++)
#pragma unroll
        for (int nt = 0; nt < 3; nt++) {
            int col = w*24 + nt*8 + 2*t4;
            int r0 = mt*16 + g;
            Cs[r0*97 + col]       = acc[mt][nt][0];
            Cs[r0*97 + col + 1]   = acc[mt][nt][1];
            Cs[(r0+8)*97 + col]   = acc[mt][nt][2];
            Cs[(r0+8)*97 + col+1] = acc[mt][nt][3];
        }
    __syncthreads();

    // gates: each thread 8 (b, j) pairs; consecutive lanes -> consecutive j
#pragma unroll
    for (int l = 0; l < 8; l++) {
        int b = l*4 + w;
        int j = lane;
        float pr = Cs[b*97 + j]      + bhh[j0 + j];
        float pz = Cs[b*97 + 32 + j] + bhh[HH + j0 + j];
        float pn = Cs[b*97 + 64 + j] + bhh[2*HH + j0 + j];
        const float* xir = xi + ((size_t)b*TT + t)*H3 + j0 + j;
        float r  = 1.0f / (1.0f + expf(-(xir[0]    + pr)));
        float z  = 1.0f / (1.0f + expf(-(xir[2048] + pz)));
        float nn = tanhf(xir[4096] + r * pn);
        float hp = holdf[(size_t)b*HH + j0 + j];
        float hv = (1.0f - z) * nn + z * hp;
        newf[(size_t)b*HH + j0 + j] = hv;
        newh[(size_t)b*HH + j0 + j] = __float2half(hv);
    }
}

// ---------------- projection + l2norm: out[enc*4096 + b*128 + d] ----------------
__global__ __launch_bounds__(128)
void proj_l2(const float* __restrict__ wq, const float* __restrict__ bq, float* __restrict__ out) {
    const int enc = blockIdx.y, b = blockIdx.x, d = threadIdx.x;
    const float* h = (enc ? g_hk[0] : g_hq[0]) + (size_t)b * HH;
    float acc = bq[d];
#pragma unroll 4
    for (int k = 0; k < HH; k++)
        acc = fmaf(fmaxf(h[k], 0.0f), wq[(size_t)k*CDIM + d], acc);
    __shared__ float sh[128];
    sh[d] = acc * acc;
    __syncthreads();
#pragma unroll
    for (int o = 64; o; o >>= 1) { if (d < o) sh[d] += sh[d + o]; __syncthreads(); }
    out[enc*4096 + b*CDIM + d] = acc * rsqrtf(sh[0]);
}

// ---------------- queue: copy, slot metadata, scatter, ptrs ----------------
__global__ void queue_copy(const float* __restrict__ q, float* __restrict__ out) {
    const float4* src = (const float4*)q;
    float4* dst = (float4*)(out + OUT_QUEUE);
    for (int i = blockIdx.x*blockDim.x + threadIdx.x; i < (CC*CDIM*KQ)/4; i += gridDim.x*blockDim.x)
        dst[i] = src[i];
}
__global__ void queue_meta(const float* __restrict__ targets, const int* __restrict__ ptrs,
                           float* __restrict__ out) {
    int c = threadIdx.x;
    if (c < CC) {
        int cnt = 0;
        int p = ptrs[c];
        for (int b = 0; b < BB; b++) {
            if (targets[b*CC + c] > 0.5f) { g_slot[b*CC + c] = (p + cnt) % KQ; cnt++; }
            else                            g_slot[b*CC + c] = -1;
        }
        out[OUT_PTR + c] = (float)((p + cnt) % KQ);
    }
}
__global__ __launch_bounds__(128)
void queue_scatter(float* __restrict__ out) {
    int bc = blockIdx.x;
    int b = bc / CC, c = bc % CC;
    int s = g_slot[b*CC + c];
    if (s < 0) return;
    int d = threadIdx.x;
    float v = out[OUT_K + b*CDIM + d];
    out[OUT_QUEUE + (size_t)c*CDIM*KQ + (size_t)d*KQ + s] = v;
}

// ---------------- host launch ----------------
extern "C" void kernel_launch(void* const* d_in, const int* in_sizes, int n_in,
                              void* d_out, int out_size) {
    const float* rgb    = (const float*)d_in[0];
    const float* flow   = (const float*)d_in[1];
    const float* rmask  = (const float*)d_in[2];
    const float* targets= (const float*)d_in[3];
    const float* w1_q   = (const float*)d_in[4];
    const float* b1_q   = (const float*)d_in[5];
    const float* gv_q   = (const float*)d_in[6];
    const float* be_q   = (const float*)d_in[7];
    const float* wih_q  = (const float*)d_in[8];
    const float* whh_q  = (const float*)d_in[9];
    const float* bih_q  = (const float*)d_in[10];
    const float* bhh_q  = (const float*)d_in[11];
    const float* w1_k   = (const float*)d_in[12];
    const float* b1_k   = (const float*)d_in[13];
    const float* gv_k   = (const float*)d_in[14];
    const float* be_k   = (const float*)d_in[15];
    const float* wih_k  = (const float*)d_in[16];
    const float* whh_k  = (const float*)d_in[17];
    const float* bih_k  = (const float*)d_in[18];
    const float* bhh_k  = (const float*)d_in[19];
    const float* wq     = (const float*)d_in[20];
    const float* bq     = (const float*)d_in[21];
    int ptrs_idx = (in_sizes[22] == CC) ? 22 : 23;
    int queues_idx = 45 - ptrs_idx;
    const int*   ptrs   = (const int*)d_in[ptrs_idx];
    const float* queues = (const float*)d_in[queues_idx];
    float* out = (float*)d_out;

    const int GEMM_SMEM = 2 * 2 * 128 * HS * 2;                            // 40960
    const int GRU_SMEM  = (2*32*HS + 2*96*HS) * 2 + 32*97*4;               // 32896
    cudaFuncSetAttribute(gemm_fp16,    cudaFuncAttributeMaxDynamicSharedMemorySize, GEMM_SMEM);
    cudaFuncSetAttribute(gru_step_mma, cudaFuncAttributeMaxDynamicSharedMemorySize, GRU_SMEM);

    __half *p_w1qT, *p_w1kT, *p_wihq, *p_wihk, *p_whhq, *p_whhk;
    __half *p_xq, *p_xk, *p_x1q, *p_x1k;
    float *p_y1q, *p_y1k, *p_xiq, *p_xik;
    float *p_b1k, *p_gk, *p_bek, *p_bihk;
    cudaGetSymbolAddress((void**)&p_w1qT, g_w1qT);
    cudaGetSymbolAddress((void**)&p_w1kT, g_w1kT);
    cudaGetSymbolAddress((void**)&p_wihq, g_wihq);
    cudaGetSymbolAddress((void**)&p_wihk, g_wihk);
    cudaGetSymbolAddress((void**)&p_whhq, g_whhq);
    cudaGetSymbolAddress((void**)&p_whhk, g_whhk);
    cudaGetSymbolAddress((void**)&p_xq,   g_xq);
    cudaGetSymbolAddress((void**)&p_xk,   g_xk);
    cudaGetSymbolAddress((void**)&p_y1q,  g_y1q);
    cudaGetSymbolAddress((void**)&p_y1k,  g_y1k);
    cudaGetSymbolAddress((void**)&p_x1q,  g_x1q);
    cudaGetSymbolAddress((void**)&p_x1k,  g_x1k);
    cudaGetSymbolAddress((void**)&p_xiq,  g_xiq);
    cudaGetSymbolAddress((void**)&p_xik,  g_xik);
    cudaGetSymbolAddress((void**)&p_b1k,  g_b1k);
    cudaGetSymbolAddress((void**)&p_gk,   g_gk);
    cudaGetSymbolAddress((void**)&p_bek,  g_bek);
    cudaGetSymbolAddress((void**)&p_bihk, g_bihk);

    // 1. weight prep: transpose / momentum / fp16 conversion
    {
        dim3 tb(32, 8);
        dim3 tg(EE/32, DIN/32);   // (32, 128)
        transpose_mix_half<<<tg, tb>>>(w1_q, w1_q, 1.0f, 0.0f, p_w1qT, DIN, EE);
        transpose_mix_half<<<tg, tb>>>(w1_k, w1_q, MOM, 1.0f - MOM, p_w1kT, DIN, EE);
        mix_half<<<2048, 256>>>((const float4*)wih_q, (const float4*)wih_q, 1.0f, 0.0f,
                                (uint2*)p_wihq, (H3*EE)/4);
        mix_half<<<2048, 256>>>((const float4*)wih_k, (const float4*)wih_q, MOM, 1.0f - MOM,
                                (uint2*)p_wihk, (H3*EE)/4);
        mix_half<<<4096, 256>>>((const float4*)whh_q, (const float4*)whh_q, 1.0f, 0.0f,
                                (uint2*)p_whhq, (H3*HH)/4);
        mix_half<<<4096, 256>>>((const float4*)whh_k, (const float4*)whh_q, MOM, 1.0f - MOM,
                                (uint2*)p_whhk, (H3*HH)/4);
        mom_vec<<<(H3 + 255)/256, 256>>>(b1_k, b1_q, gv_k, gv_q, be_k, be_q,
                                         bih_k, bih_q, bhh_k, bhh_q);
    }

    // 2. build inputs (fp16)
    build_inputs<<<8192, 256>>>((const float4*)rgb, (const float4*)flow, rmask);

    // 3. GEMM1 -> LN/ReLU -> GEMM2 (fp16 tensor cores, fp32 accum)
    {
        dim3 g1(EE/128, BT/128);    // (8, 32)
        gemm_fp16<<<g1, 256, GEMM_SMEM>>>(p_xq, p_w1qT, b1_q,  p_y1q, BT, EE, DIN);
        gemm_fp16<<<g1, 256, GEMM_SMEM>>>(p_xk, p_w1kT, p_b1k, p_y1k, BT, EE, DIN);

        ln_relu<<<BT, 256>>>(p_y1q, p_x1q, gv_q, be_q);
        ln_relu<<<BT, 256>>>(p_y1k, p_x1k, p_gk, p_bek);

        dim3 g2(H3/128, BT/128);    // (48, 32)
        gemm_fp16<<<g2, 256, GEMM_SMEM>>>(p_x1q, p_wihq, bih_q,  p_xiq, BT, H3, EE);
        gemm_fp16<<<g2, 256, GEMM_SMEM>>>(p_x1k, p_wihk, p_bihk, p_xik, BT, H3, EE);
    }

    // 4. GRU recurrence (128 steps, fp16 tensor-core hh GEMM + fused gates)
    h_init<<<(BB*HH + 255)/256, 256>>>();
    for (int t = 0; t < TT; t++)
        gru_step_mma<<<dim3(HH/32, 2), 128, GRU_SMEM>>>(t, t & 1, bhh_q);

    // 5. projection + l2norm -> q_cls, k_cls
    proj_l2<<<dim3(BB, 2), 128>>>(wq, bq, out);

    // 6. queue: copy, metadata (+new_ptrs), scatter k_cls
    queue_copy<<<2816, 256>>>(queues, out);
    queue_meta<<<1, 32>>>(targets, ptrs, out);
    queue_scatter<<<BB*CC, 128>>>(out);
}

// round 9
// speedup vs baseline: 4.8514x; 1.0219x over previous
#include <cuda_runtime.h>
#include <cuda_fp16.h>
#include <math.h>
#include <stdint.h>

// ---------------- problem constants ----------------
#define BB   32
#define TT   128
#define BT   4096          // B*T
#define DIN  4096          // D_RGB + D_FLOW
#define EE   1024
#define HH   2048
#define H3   6144
#define CC   22
#define KQ   1024
#define CDIM 128
#define MOM  0.999f

// output offsets (float32 concat: q_cls, k_cls, new_queues, new_ptrs)
#define OUT_Q      0
#define OUT_K      4096
#define OUT_QUEUE  8192
#define OUT_PTR    (8192 + CC*CDIM*KQ)

#define HS 40   // SMEM row stride in halves (80B): 16B-aligned rows, conflict-free frags

// ---------------- device scratch (zero-init .bss; allowed) ----------------
__device__ __align__(16) __half g_w1qT[EE*DIN];   // w1_q^T [E][DIN] fp16
__device__ __align__(16) __half g_w1kT[EE*DIN];   // momentum key w1^T fp16
__device__ __align__(16) __half g_wihq[H3*EE];
__device__ __align__(16) __half g_wihk[H3*EE];
__device__ __align__(16) __half g_whhq[H3*HH];
__device__ __align__(16) __half g_whhk[H3*HH];
__device__ float  g_b1k [EE];
__device__ float  g_gk  [EE];
__device__ float  g_bek [EE];
__device__ float  g_bihk[H3];
__device__ float  g_bhhk[H3];

__device__ __align__(16) __half g_xq  [BT*DIN];   // masked concat (query) fp16
__device__ __align__(16) __half g_xk  [BT*DIN];   // unmasked concat (key) fp16
__device__ float  g_y1q [BT*EE];                  // GEMM1 out fp32
__device__ float  g_y1k [BT*EE];
__device__ __align__(16) __half g_x1q [BT*EE];    // LN+ReLU out fp16
__device__ __align__(16) __half g_x1k [BT*EE];
__device__ float  g_xiq [BT*H3];                  // GRU input preacts fp32
__device__ float  g_xik [BT*H3];

__device__ float  g_hq [2][BB*HH];                // fp32 hidden state (ping-pong)
__device__ float  g_hk [2][BB*HH];
__device__ __align__(16) __half g_hqh[2][BB*HH];  // fp16 copy for mma
__device__ __align__(16) __half g_hkh[2][BB*HH];

__device__ int    g_slot[BB*CC];

// ---------------- helpers ----------------
__device__ __forceinline__ void cp16(void* s, const void* g) {
    uint32_t sa = (uint32_t)__cvta_generic_to_shared(s);
    asm volatile("cp.async.cg.shared.global [%0], [%1], 16;" :: "r"(sa), "l"(g));
}
__device__ __forceinline__ void cp_commit() {
    asm volatile("cp.async.commit_group;");
}
template<int N> __device__ __forceinline__ void cp_wait() {
    asm volatile("cp.async.wait_group %0;" :: "n"(N));
}
__device__ __forceinline__ void mma_fp16(float* c, const uint32_t* a, const uint32_t* b) {
    asm volatile("mma.sync.aligned.m16n8k16.row.col.f32.f16.f16.f32 "
                 "{%0,%1,%2,%3},{%4,%5,%6,%7},{%8,%9},{%0,%1,%2,%3};"
                 : "+f"(c[0]), "+f"(c[1]), "+f"(c[2]), "+f"(c[3])
                 : "r"(a[0]), "r"(a[1]), "r"(a[2]), "r"(a[3]),
                   "r"(b[0]), "r"(b[1]));
}
__device__ __forceinline__ uint32_t pack2(float a, float b) {
    __half2 h = __floats2half2_rn(a, b);
    return *(uint32_t*)&h;
}

// ---------------- prep kernels ----------------
__global__ void mix_half(const float4* __restrict__ sa, const float4* __restrict__ sb,
                         float fa, float fb, uint2* __restrict__ dst, int n4) {
    for (int i = blockIdx.x*blockDim.x + threadIdx.x; i < n4; i += gridDim.x*blockDim.x) {
        float4 a = sa[i], b = sb[i];
        uint2 o;
        o.x = pack2(fa*a.x + fb*b.x, fa*a.y + fb*b.y);
        o.y = pack2(fa*a.z + fb*b.z, fa*a.w + fb*b.w);
        dst[i] = o;
    }
}
__global__ __launch_bounds__(256)
void transpose_mix_half(const float* __restrict__ sa, const float* __restrict__ sb,
                        float fa, float fb, __half* __restrict__ dst, int Kd, int Nd) {
    __shared__ float sh[32][33];
    int tx = threadIdx.x, ty = threadIdx.y;       // block (32,8)
    int n0 = blockIdx.x*32, k0 = blockIdx.y*32;
#pragma unroll
    for (int i = 0; i < 4; i++) {
        size_t idx = (size_t)(k0 + ty + i*8)*Nd + n0 + tx;
        sh[ty + i*8][tx] = fa*sa[idx] + fb*sb[idx];
    }
    __syncthreads();
#pragma unroll
    for (int i = 0; i < 4; i++)
        dst[(size_t)(n0 + ty + i*8)*Kd + k0 + tx] = __float2half(sh[tx][ty + i*8]);
}
__global__ void mom_vec(const float* b1k, const float* b1q,
                        const float* gk,  const float* gq,
                        const float* bek, const float* beq,
                        const float* bihk,const float* bihq,
                        const float* bhhk,const float* bhhq) {
    int i = blockIdx.x*blockDim.x + threadIdx.x;
    if (i < EE) {
        g_b1k[i] = MOM*b1k[i] + (1.0f-MOM)*b1q[i];
        g_gk [i] = MOM*gk [i] + (1.0f-MOM)*gq [i];
        g_bek[i] = MOM*bek[i] + (1.0f-MOM)*beq[i];
    }
    if (i < H3) {
        g_bihk[i] = MOM*bihk[i] + (1.0f-MOM)*bihq[i];
        g_bhhk[i] = MOM*bhhk[i] + (1.0f-MOM)*bhhq[i];
    }
}

// ---------------- build masked / unmasked concat inputs (fp16) ----------------
__global__ void build_inputs(const float4* __restrict__ rgb, const float4* __restrict__ flow,
                             const float* __restrict__ rmask) {
    uint2* xq = (uint2*)g_xq;
    uint2* xk = (uint2*)g_xk;
    for (int i4 = blockIdx.x*blockDim.x + threadIdx.x; i4 < (BT*DIN)/4; i4 += gridDim.x*blockDim.x) {
        int bt = i4 >> 10;
        int c4 = i4 & 1023;
        int t  = bt & (TT-1);
        float m = (t == TT-1 || rmask[bt] > 0.25f) ? 1.0f : 0.0f;
        float4 v = (c4 < 512) ? rgb[(size_t)bt*512 + c4] : flow[(size_t)bt*512 + (c4-512)];
        uint2 ok; ok.x = pack2(v.x, v.y); ok.y = pack2(v.z, v.w);
        uint2 oq; oq.x = pack2(v.x*m, v.y*m); oq.y = pack2(v.z*m, v.w*m);
        xq[i4] = oq;
        xk[i4] = ok;
    }
}

// ---------------- fp16 MMA GEMM: C[M,N] = A[M,K]h * B[N,K]h^T + bias ----------------
// 128x128 block tile, k-tile 32 halves, cp.async 3-stage ring, 8 warps.
__global__ __launch_bounds__(256)
void gemm_fp16(const __half* __restrict__ A, const __half* __restrict__ B,
               const float* __restrict__ bias, float* __restrict__ C,
               int M, int N, int K) {
    extern __shared__ __half smh[];
    __half* As = smh;                  // [3][128][HS]
    __half* Bs = smh + 3*128*HS;       // [3][128][HS]

    const int tid = threadIdx.x;
    const int w = tid >> 5, lane = tid & 31;
    const int g = lane >> 2, t4 = lane & 3;
    const int wm = w >> 1, wn = w & 1;
    const int m0 = blockIdx.y * 128, n0 = blockIdx.x * 128;
    const int lr = tid >> 1, lseg = (tid & 1) * 2;

    float acc[2][8][4];
#pragma unroll
    for (int mt = 0; mt < 2; mt++)
#pragma unroll
        for (int nt = 0; nt < 8; nt++)
#pragma unroll
            for (int i = 0; i < 4; i++) acc[mt][nt][i] = 0.0f;

    auto loadStage = [&](int s, int k0) {
        const __half* Ag = A + (size_t)m0 * K + k0;
        const __half* Bg = B + (size_t)n0 * K + k0;
        __half* as = As + s*128*HS;
        __half* bs = Bs + s*128*HS;
#pragma unroll
        for (int i = 0; i < 2; i++) {
            int seg = lseg + i;                       // 0..3
            cp16(&as[lr*HS + seg*8], Ag + (size_t)lr*K + seg*8);
            cp16(&bs[lr*HS + seg*8], Bg + (size_t)lr*K + seg*8);
        }
        cp_commit();
    };

    const int KT = K >> 5;
    loadStage(0, 0);
    loadStage(1, 32);
    int s_use = 0, s_load = 2;
    for (int kt = 0; kt < KT; kt++) {
        if (kt + 2 < KT) { loadStage(s_load, (kt + 2) << 5); }
        else             { cp_commit(); }                      // empty group keeps count
        if (++s_load == 3) s_load = 0;
        cp_wait<2>();
        __syncthreads();
        const __half* as = As + s_use*128*HS;
        const __half* bs = Bs + s_use*128*HS;
#pragma unroll
        for (int ks = 0; ks < 2; ks++) {
            int kc = ks*16 + 2*t4;
            uint32_t a[2][4], b[8][2];
#pragma unroll
            for (int mt = 0; mt < 2; mt++) {
                int mr = wm*32 + mt*16 + g;
                a[mt][0] = *(const uint32_t*)&as[mr*HS + kc];
                a[mt][1] = *(const uint32_t*)&as[(mr+8)*HS + kc];
                a[mt][2] = *(const uint32_t*)&as[mr*HS + kc + 8];
                a[mt][3] = *(const uint32_t*)&as[(mr+8)*HS + kc + 8];
            }
#pragma unroll
            for (int nt = 0; nt < 8; nt++) {
                int nr = wn*64 + nt*8 + g;
                b[nt][0] = *(const uint32_t*)&bs[nr*HS + kc];
                b[nt][1] = *(const uint32_t*)&bs[nr*HS + kc + 8];
            }
#pragma unroll
            for (int mt = 0; mt < 2; mt++)
#pragma unroll
                for (int nt = 0; nt < 8; nt++)
                    mma_fp16(acc[mt][nt], a[mt], b[nt]);
        }
        if (++s_use == 3) s_use = 0;
        __syncthreads();
    }
    // epilogue: + bias
#pragma unroll
    for (int mt = 0; mt < 2; mt++)
#pragma unroll
        for (int nt = 0; nt < 8; nt++) {
            int col = n0 + wn*64 + nt*8 + 2*t4;
            float b0 = bias[col], b1 = bias[col+1];
            int r0 = m0 + wm*32 + mt*16 + g;
            float2 v0 = make_float2(acc[mt][nt][0] + b0, acc[mt][nt][1] + b1);
            float2 v1 = make_float2(acc[mt][nt][2] + b0, acc[mt][nt][3] + b1);
            *(float2*)(C + (size_t)r0*N + col)     = v0;
            *(float2*)(C + (size_t)(r0+8)*N + col) = v1;
        }
}

// ---------------- LayerNorm + ReLU, fp32 in -> fp16 out, rows of EE=1024 ----------
__global__ __launch_bounds__(256)
void ln_relu(const float* __restrict__ x, __half* __restrict__ xo,
             const float* __restrict__ g, const float* __restrict__ be) {
    int row = blockIdx.x;
    int tid = threadIdx.x;
    const float4* xr = (const float4*)(x + (size_t)row * EE);
    float4 v = xr[tid];
    float s  = v.x + v.y + v.z + v.w;
    float ss = v.x*v.x + v.y*v.y + v.z*v.z + v.w*v.w;
#pragma unroll
    for (int o = 16; o; o >>= 1) {
        s  += __shfl_xor_sync(0xffffffffu, s,  o);
        ss += __shfl_xor_sync(0xffffffffu, ss, o);
    }
    __shared__ float sh_s[8], sh_ss[8];
    if ((tid & 31) == 0) { sh_s[tid >> 5] = s; sh_ss[tid >> 5] = ss; }
    __syncthreads();
    float S = 0.0f, SS = 0.0f;
#pragma unroll
    for (int w = 0; w < 8; w++) { S += sh_s[w]; SS += sh_ss[w]; }
    float mu   = S * (1.0f / EE);
    float var  = SS * (1.0f / EE) - mu * mu;
    float rstd = rsqrtf(var + 1e-5f);
    int c = tid * 4;
    float4 gg = *(const float4*)(g  + c);
    float4 bb = *(const float4*)(be + c);
    uint2 o;
    o.x = pack2(fmaxf((v.x - mu) * rstd * gg.x + bb.x, 0.0f),
                fmaxf((v.y - mu) * rstd * gg.y + bb.y, 0.0f));
    o.y = pack2(fmaxf((v.z - mu) * rstd * gg.z + bb.z, 0.0f),
                fmaxf((v.w - mu) * rstd * gg.w + bb.w, 0.0f));
    ((uint2*)(xo + (size_t)row * EE))[tid] = o;
}

// ---------------- init hidden state ----------------
__global__ void h_init() {
    int i = blockIdx.x*blockDim.x + threadIdx.x;
    if (i < BB*HH) {
        g_hq[0][i] = 0.0f; g_hk[0][i] = 0.0f;
        g_hqh[0][i] = __float2half(0.0f); g_hkh[0][i] = __float2half(0.0f);
    }
}

// ---------------- one GRU step via fp16 MMA, 4-stage cp.async ring ----------------
// grid (HH/32, 2 encoders), 128 threads (4 warps). Block computes
// C[32, 96] = h[32,2048] @ whh[{r,z,n} rows j0..j0+31, 2048]^T, then gates.
__global__ __launch_bounds__(128)
void gru_step_mma(int t, int par, const float* __restrict__ bhh_qp) {
    extern __shared__ __half smh[];
    __half* Hsm = smh;                        // [4][32][HS]
    __half* Wsm = smh + 4*32*HS;              // [4][96][HS]
    float*  Cs  = (float*)(smh + 4*32*HS + 4*96*HS);   // [32][97]

    const int enc = blockIdx.y;
    const int j0  = blockIdx.x * 32;
    const int tid = threadIdx.x;
    const int w = tid >> 5, lane = tid & 31;
    const int g = lane >> 2, t4 = lane & 3;

    const __half* whh  = enc ? g_whhk : g_whhq;
    const float*  bhh  = enc ? g_bhhk : bhh_qp;
    const float*  xi   = enc ? g_xik  : g_xiq;
    const float*  holdf= enc ? g_hk [par] : g_hq [par];
    const __half* holdh= enc ? g_hkh[par] : g_hqh[par];
    float*  newf = enc ? g_hk [par ^ 1] : g_hq [par ^ 1];
    __half* newh = enc ? g_hkh[par ^ 1] : g_hqh[par ^ 1];

    float acc[2][3][4];
#pragma unroll
    for (int mt = 0; mt < 2; mt++)
#pragma unroll
        for (int nt = 0; nt < 3; nt++)
#pragma unroll
            for (int i = 0; i < 4; i++) acc[mt][nt][i] = 0.0f;

    auto loadStage = [&](int s, int k0) {
        __half* hs = Hsm + s*32*HS;
        __half* ws = Wsm + s*96*HS;
        {   // H: 32 rows x 32 halves = 128 segs; 1 per thread
            int row = tid >> 2, seg = tid & 3;
            cp16(&hs[row*HS + seg*8], holdh + (size_t)row*HH + k0 + seg*8);
        }
#pragma unroll
        for (int l = 0; l < 3; l++) {             // W: 96 x 32 = 384 segs; 3 per thread
            int idx = tid + l*128;
            int row = idx >> 2, seg = idx & 3;
            int n = (row >> 5)*HH + j0 + (row & 31);
            cp16(&ws[row*HS + seg*8], whh + (size_t)n*HH + k0 + seg*8);
        }
        cp_commit();
    };

    const int KT = HH / 32;   // 64
    loadStage(0, 0);
    loadStage(1, 32);
    loadStage(2, 64);
    for (int kt = 0; kt < KT; kt++) {
        if (kt + 3 < KT) loadStage((kt + 3) & 3, (kt + 3) * 32);
        else             cp_commit();                // empty group keeps count
        cp_wait<3>();
        __syncthreads();
        const __half* hs = Hsm + (kt & 3)*32*HS;
        const __half* ws = Wsm + (kt & 3)*96*HS;
#pragma unroll
        for (int ks = 0; ks < 2; ks++) {
            int kc = ks*16 + 2*t4;
            uint32_t a[2][4], b[3][2];
#pragma unroll
            for (int mt = 0; mt < 2; mt++) {
                int mr = mt*16 + g;
                a[mt][0] = *(const uint32_t*)&hs[mr*HS + kc];
                a[mt][1] = *(const uint32_t*)&hs[(mr+8)*HS + kc];
                a[mt][2] = *(const uint32_t*)&hs[mr*HS + kc + 8];
                a[mt][3] = *(const uint32_t*)&hs[(mr+8)*HS + kc + 8];
            }
#pragma unroll
            for (int nt = 0; nt < 3; nt++) {
                int nr = w*24 + nt*8 + g;
                b[nt][0] = *(const uint32_t*)&ws[nr*HS + kc];
                b[nt][1] = *(const uint32_t*)&ws[nr*HS + kc + 8];
            }
#pragma unroll
            for (int mt = 0; mt < 2; mt++)
#pragma unroll
                for (int nt = 0; nt < 3; nt++)
                    mma_fp16(acc[mt][nt], a[mt], b[nt]);
        }
        __syncthreads();
    }

    // stage accumulators: Cs[b][c], c = gate*32 + j_local
#pragma unroll
    for (int mt = 0; mt < 2; mt++)
#pragma unroll
        for (int nt = 0; nt < 3; nt++) {
            int col = w*24 + nt*8 + 2*t4;
            int r0 = mt*16 + g;
            Cs[r0*97 + col]       = acc[mt][nt][0];
            Cs[r0*97 + col + 1]   = acc[mt][nt][1];
            Cs[(r0+8)*97 + col]   = acc[mt][nt][2];
            Cs[(r0+8)*97 + col+1] = acc[mt][nt][3];
        }
    __syncthreads();

    // gates: each thread 8 (b, j) pairs; consecutive lanes -> consecutive j
#pragma unroll
    for (int l = 0; l < 8; l++) {
        int b = l*4 + w;
        int j = lane;
        float pr = Cs[b*97 + j]      + bhh[j0 + j];
        float pz = Cs[b*97 + 32 + j] + bhh[HH + j0 + j];
        float pn = Cs[b*97 + 64 + j] + bhh[2*HH + j0 + j];
        const float* xir = xi + ((size_t)b*TT + t)*H3 + j0 + j;
        float r  = 1.0f / (1.0f + expf(-(xir[0]    + pr)));
        float z  = 1.0f / (1.0f + expf(-(xir[2048] + pz)));
        float nn = tanhf(xir[4096] + r * pn);
        float hp = holdf[(size_t)b*HH + j0 + j];
        float hv = (1.0f - z) * nn + z * hp;
        newf[(size_t)b*HH + j0 + j] = hv;
        newh[(size_t)b*HH + j0 + j] = __float2half(hv);
    }
}

// ---------------- projection + l2norm: out[enc*4096 + b*128 + d] ----------------
__global__ __launch_bounds__(128)
void proj_l2(const float* __restrict__ wq, const float* __restrict__ bq, float* __restrict__ out) {
    const int enc = blockIdx.y, b = blockIdx.x, d = threadIdx.x;
    const float* h = (enc ? g_hk[0] : g_hq[0]) + (size_t)b * HH;
    float acc = bq[d];
#pragma unroll 4
    for (int k = 0; k < HH; k++)
        acc = fmaf(fmaxf(h[k], 0.0f), wq[(size_t)k*CDIM + d], acc);
    __shared__ float sh[128];
    sh[d] = acc * acc;
    __syncthreads();
#pragma unroll
    for (int o = 64; o; o >>= 1) { if (d < o) sh[d] += sh[d + o]; __syncthreads(); }
    out[enc*4096 + b*CDIM + d] = acc * rsqrtf(sh[0]);
}

// ---------------- queue: copy, slot metadata, scatter, ptrs ----------------
__global__ void queue_copy(const float* __restrict__ q, float* __restrict__ out) {
    const float4* src = (const float4*)q;
    float4* dst = (float4*)(out + OUT_QUEUE);
    for (int i = blockIdx.x*blockDim.x + threadIdx.x; i < (CC*CDIM*KQ)/4; i += gridDim.x*blockDim.x)
        dst[i] = src[i];
}
__global__ void queue_meta(const float* __restrict__ targets, const int* __restrict__ ptrs,
                           float* __restrict__ out) {
    int c = threadIdx.x;
    if (c < CC) {
        int cnt = 0;
        int p = ptrs[c];
        for (int b = 0; b < BB; b++) {
            if (targets[b*CC + c] > 0.5f) { g_slot[b*CC + c] = (p + cnt) % KQ; cnt++; }
            else                            g_slot[b*CC + c] = -1;
        }
        out[OUT_PTR + c] = (float)((p + cnt) % KQ);
    }
}
__global__ __launch_bounds__(128)
void queue_scatter(float* __restrict__ out) {
    int bc = blockIdx.x;
    int b = bc / CC, c = bc % CC;
    int s = g_slot[b*CC + c];
    if (s < 0) return;
    int d = threadIdx.x;
    float v = out[OUT_K + b*CDIM + d];
    out[OUT_QUEUE + (size_t)c*CDIM*KQ + (size_t)d*KQ + s] = v;
}

// ---------------- host launch ----------------
extern "C" void kernel_launch(void* const* d_in, const int* in_sizes, int n_in,
                              void* d_out, int out_size) {
    const float* rgb    = (const float*)d_in[0];
    const float* flow   = (const float*)d_in[1];
    const float* rmask  = (const float*)d_in[2];
    const float* targets= (const float*)d_in[3];
    const float* w1_q   = (const float*)d_in[4];
    const float* b1_q   = (const float*)d_in[5];
    const float* gv_q   = (const float*)d_in[6];
    const float* be_q   = (const float*)d_in[7];
    const float* wih_q  = (const float*)d_in[8];
    const float* whh_q  = (const float*)d_in[9];
    const float* bih_q  = (const float*)d_in[10];
    const float* bhh_q  = (const float*)d_in[11];
    const float* w1_k   = (const float*)d_in[12];
    const float* b1_k   = (const float*)d_in[13];
    const float* gv_k   = (const float*)d_in[14];
    const float* be_k   = (const float*)d_in[15];
    const float* wih_k  = (const float*)d_in[16];
    const float* whh_k  = (const float*)d_in[17];
    const float* bih_k  = (const float*)d_in[18];
    const float* bhh_k  = (const float*)d_in[19];
    const float* wq     = (const float*)d_in[20];
    const float* bq     = (const float*)d_in[21];
    int ptrs_idx = (in_sizes[22] == CC) ? 22 : 23;
    int queues_idx = 45 - ptrs_idx;
    const int*   ptrs   = (const int*)d_in[ptrs_idx];
    const float* queues = (const float*)d_in[queues_idx];
    float* out = (float*)d_out;

    const int GEMM_SMEM = 3 * 2 * 128 * HS * 2;                            // 61440
    const int GRU_SMEM  = (4*32*HS + 4*96*HS) * 2 + 32*97*4;               // 53376
    cudaFuncSetAttribute(gemm_fp16,    cudaFuncAttributeMaxDynamicSharedMemorySize, GEMM_SMEM);
    cudaFuncSetAttribute(gru_step_mma, cudaFuncAttributeMaxDynamicSharedMemorySize, GRU_SMEM);

    __half *p_w1qT, *p_w1kT, *p_wihq, *p_wihk, *p_whhq, *p_whhk;
    __half *p_xq, *p_xk, *p_x1q, *p_x1k;
    float *p_y1q, *p_y1k, *p_xiq, *p_xik;
    float *p_b1k, *p_gk, *p_bek, *p_bihk;
    cudaGetSymbolAddress((void**)&p_w1qT, g_w1qT);
    cudaGetSymbolAddress((void**)&p_w1kT, g_w1kT);
    cudaGetSymbolAddress((void**)&p_wihq, g_wihq);
    cudaGetSymbolAddress((void**)&p_wihk, g_wihk);
    cudaGetSymbolAddress((void**)&p_whhq, g_whhq);
    cudaGetSymbolAddress((void**)&p_whhk, g_whhk);
    cudaGetSymbolAddress((void**)&p_xq,   g_xq);
    cudaGetSymbolAddress((void**)&p_xk,   g_xk);
    cudaGetSymbolAddress((void**)&p_y1q,  g_y1q);
    cudaGetSymbolAddress((void**)&p_y1k,  g_y1k);
    cudaGetSymbolAddress((void**)&p_x1q,  g_x1q);
    cudaGetSymbolAddress((void**)&p_x1k,  g_x1k);
    cudaGetSymbolAddress((void**)&p_xiq,  g_xiq);
    cudaGetSymbolAddress((void**)&p_xik,  g_xik);
    cudaGetSymbolAddress((void**)&p_b1k,  g_b1k);
    cudaGetSymbolAddress((void**)&p_gk,   g_gk);
    cudaGetSymbolAddress((void**)&p_bek,  g_bek);
    cudaGetSymbolAddress((void**)&p_bihk, g_bihk);

    // 1. weight prep: transpose / momentum / fp16 conversion
    {
        dim3 tb(32, 8);
        dim3 tg(EE/32, DIN/32);   // (32, 128)
        transpose_mix_half<<<tg, tb>>>(w1_q, w1_q, 1.0f, 0.0f, p_w1qT, DIN, EE);
        transpose_mix_half<<<tg, tb>>>(w1_k, w1_q, MOM, 1.0f - MOM, p_w1kT, DIN, EE);
        mix_half<<<2048, 256>>>((const float4*)wih_q, (const float4*)wih_q, 1.0f, 0.0f,
                                (uint2*)p_wihq, (H3*EE)/4);
        mix_half<<<2048, 256>>>((const float4*)wih_k, (const float4*)wih_q, MOM, 1.0f - MOM,
                                (uint2*)p_wihk, (H3*EE)/4);
        mix_half<<<4096, 256>>>((const float4*)whh_q, (const float4*)whh_q, 1.0f, 0.0f,
                                (uint2*)p_whhq, (H3*HH)/4);
        mix_half<<<4096, 256>>>((const float4*)whh_k, (const float4*)whh_q, MOM, 1.0f - MOM,
                                (uint2*)p_whhk, (H3*HH)/4);
        mom_vec<<<(H3 + 255)/256, 256>>>(b1_k, b1_q, gv_k, gv_q, be_k, be_q,
                                         bih_k, bih_q, bhh_k, bhh_q);
    }

    // 2. build inputs (fp16)
    build_inputs<<<8192, 256>>>((const float4*)rgb, (const float4*)flow, rmask);

    // 3. GEMM1 -> LN/ReLU -> GEMM2 (fp16 tensor cores, fp32 accum)
    {
        dim3 g1(EE/128, BT/128);    // (8, 32)
        gemm_fp16<<<g1, 256, GEMM_SMEM>>>(p_xq, p_w1qT, b1_q,  p_y1q, BT, EE, DIN);
        gemm_fp16<<<g1, 256, GEMM_SMEM>>>(p_xk, p_w1kT, p_b1k, p_y1k, BT, EE, DIN);

        ln_relu<<<BT, 256>>>(p_y1q, p_x1q, gv_q, be_q);
        ln_relu<<<BT, 256>>>(p_y1k, p_x1k, p_gk, p_bek);

        dim3 g2(H3/128, BT/128);    // (48, 32)
        gemm_fp16<<<g2, 256, GEMM_SMEM>>>(p_x1q, p_wihq, bih_q,  p_xiq, BT, H3, EE);
        gemm_fp16<<<g2, 256, GEMM_SMEM>>>(p_x1k, p_wihk, p_bihk, p_xik, BT, H3, EE);
    }

    // 4. GRU recurrence (128 steps, fp16 tensor-core hh GEMM + fused gates)
    h_init<<<(BB*HH + 255)/256, 256>>>();
    for (int t = 0; t < TT; t++)
        gru_step_mma<<<dim3(HH/32, 2), 128, GRU_SMEM>>>(t, t & 1, bhh_q);

    // 5. projection + l2norm -> q_cls, k_cls
    proj_l2<<<dim3(BB, 2), 128>>>(wq, bq, out);

    // 6. queue: copy, metadata (+new_ptrs), scatter k_cls
    queue_copy<<<2816, 256>>>(queues, out);
    queue_meta<<<1, 32>>>(targets, ptrs, out);
    queue_scatter<<<BB*CC, 128>>>(out);
}